// round 13
// baseline (speedup 1.0000x reference)
#include <cuda_runtime.h>
#include <cuda_bf16.h>

// ---------------------------------------------------------------------------
// LSTM-VAE forward.  B=64, T=1000, IN=8, H=512, Z4=2048, LAT=128
// tf32 tensor-core GEMMs (mma.sync.m16n8k8) for xg projection + recurrence.
// Recurrence: persistent grid, software-pipelined h-exchange, CG-style barrier.
// Output layout: [recon (B,T,IN) | mu (B,LAT) | logvar (B,LAT)]
// ---------------------------------------------------------------------------

#define Bz   64
#define Tz   1000
#define INz  8
#define Hz   512
#define Z4z  2048
#define LATz 128

// ------------------------- scratch (__device__ globals) --------------------
__device__ float g_e[Bz * Tz];                       // EMA channel      (B,T)
__device__ float g_hin[(size_t)Tz * Hz * Bz];        // enc input        (T,H,B)
__device__ float g_xg[(size_t)Tz * Z4z * Bz];        // enc gate preacts (T,Z4,B)
__device__ float g_xgdec[Z4z * Bz];                  // dec gate preacts (Z4,B)
__device__ float g_hbuf[2][Hz * Bz];                 // h double buffer  ([k][b])
__device__ float g_hs[(size_t)Tz * Hz * Bz];         // dec hidden seq   (T,H,B)
__device__ float g_z[Bz * LATz];
__device__ float g_d[Bz * Hz];
__device__ unsigned g_barrier;

__device__ __forceinline__ float sigf(float x) { return 1.f / (1.f + __expf(-x)); }

// tf32 helpers ---------------------------------------------------------------
__device__ __forceinline__ float tf32r(float f) {
    unsigned u;
    asm("cvt.rna.tf32.f32 %0, %1;" : "=r"(u) : "f"(f));
    return __uint_as_float(u);
}
__device__ __forceinline__ void mma8(float* d, const unsigned* a, unsigned b0, unsigned b1) {
    asm volatile(
        "mma.sync.aligned.m16n8k8.row.col.f32.tf32.tf32.f32 "
        "{%0,%1,%2,%3},{%4,%5,%6,%7},{%8,%9},{%0,%1,%2,%3};"
        : "+f"(d[0]), "+f"(d[1]), "+f"(d[2]), "+f"(d[3])
        : "r"(a[0]), "r"(a[1]), "r"(a[2]), "r"(a[3]), "r"(b0), "r"(b1));
}

// ---------------------- EMA (parallel scan) + reset ------------------------
__global__ void k_ema(const float* __restrict__ x) {
    __shared__ float s_end[8 * 64];
    __shared__ float s_init[8 * 64];
    int tid = threadIdx.x, b = tid & 63, c = tid >> 6;

    // fused reset
    for (int i = tid; i < Hz * Bz; i += 512) { g_hbuf[0][i] = 0.f; g_hbuf[1][i] = 0.f; }
    if (tid == 0) g_barrier = 0u;

    int t0 = c * 125;
    float e = 0.f;
    for (int i = 0; i < 125; ++i) {
        int t = t0 + i;
        float v = x[((size_t)b * Tz + t) * INz + 1];
        e = (c == 0 && i == 0) ? v : (0.1f * v + 0.9f * e);
        g_e[b * Tz + t] = e;
    }
    s_end[c * 64 + b] = e;
    __syncthreads();
    if (tid < 64) {
        const float P125 = 1.906849e-6f;       // 0.9^125
        float E = s_end[0 * 64 + tid];         // chunk0 is exact
        for (int cc = 1; cc < 8; ++cc) {
            s_init[cc * 64 + tid] = E;
            E = s_end[cc * 64 + tid] + E * P125;
        }
    }
    __syncthreads();
    if (c >= 1) {
        float I = s_init[c * 64 + b];
        float pw = 0.9f;
        for (int i = 0; i < 125; ++i) {
            g_e[b * Tz + t0 + i] += I * pw;
            pw *= 0.9f;
        }
    }
}

// ---------------- input FC + ReLU + positional encoding --------------------
__global__ void __launch_bounds__(256) k_hin(const float* __restrict__ x,
                                             const float* __restrict__ w,
                                             const float* __restrict__ bias) {
    int t = blockIdx.x, ht = blockIdx.y * 64;
    __shared__ float s_x[64][8];
    __shared__ float s_w[64][8];
    __shared__ float s_b[64];
    __shared__ float s_pe[64];
    int tid = threadIdx.x;

    for (int i = tid; i < 512; i += 256) {
        int bb = i >> 3, ii = i & 7;
        float v = x[((size_t)bb * Tz + t) * INz + ii];
        if (ii == 1) v = g_e[bb * Tz + t];
        s_x[bb][ii] = v;
    }
    for (int i = tid; i < 512; i += 256) {
        int hh = i >> 3, ii = i & 7;
        s_w[hh][ii] = w[(ht + hh) * INz + ii];
    }
    if (tid < 64) {
        int h = ht + tid;
        s_b[tid] = bias[h];
        int j = h >> 1;
        float div = __expf(-(float)(2 * j) * (9.2103403719761836f / 512.f));
        float ang = (float)t * div;
        s_pe[tid] = 0.1f * ((h & 1) ? cosf(ang) : sinf(ang));
    }
    __syncthreads();

    int hh = tid >> 2, bq = tid & 3;
    for (int q = 0; q < 16; ++q) {
        int bb = bq * 16 + q;
        float a = s_b[hh];
#pragma unroll
        for (int i = 0; i < 8; ++i) a += s_w[hh][i] * s_x[bb][i];
        a = fmaxf(a, 0.f) + s_pe[hh];
        g_hin[((size_t)t * Hz + ht + hh) * Bz + bb] = a;
    }
}

// ------------- encoder gate preactivations: xg = hin @ w_ihT + b -----------
#define XG_SW_PITCH 68
#define XG_SH_PITCH 72
#define SMEM_XG ((128 * XG_SW_PITCH + 2 * 64 * XG_SH_PITCH) * 4)

__global__ void __launch_bounds__(256) k_xg(const float* __restrict__ wih,
                                            const float* __restrict__ bih,
                                            const float* __restrict__ bhh) {
    extern __shared__ float sm[];
    float* s_w = sm;                               // [128][68]
    float* s_h = sm + 128 * XG_SW_PITCH;           // [2][64][72]

    const int t0 = blockIdx.x * 2, g0 = blockIdx.y * 128;
    const int tid = threadIdx.x;
    const int wid = tid >> 5, lane = tid & 31;
    const int mg = wid >> 1, bg = wid & 1;
    const int g = lane >> 2, tg = lane & 3;

    float acc[2][2][4][4];
#pragma unroll
    for (int a = 0; a < 2; ++a)
#pragma unroll
        for (int b = 0; b < 2; ++b)
#pragma unroll
            for (int c = 0; c < 4; ++c)
#pragma unroll
                for (int d = 0; d < 4; ++d) acc[a][b][c][d] = 0.f;

    for (int kc = 0; kc < Hz; kc += 64) {
#pragma unroll
        for (int i = 0; i < 8; ++i) {
            int idx = tid + i * 256;               // 0..2047
            int r = idx >> 4, k4 = idx & 15;
            float4 v = *(const float4*)&wih[(size_t)(g0 + r) * Hz + kc + k4 * 4];
            v.x = tf32r(v.x); v.y = tf32r(v.y); v.z = tf32r(v.z); v.w = tf32r(v.w);
            *(float4*)&s_w[r * XG_SW_PITCH + k4 * 4] = v;
        }
#pragma unroll
        for (int i = 0; i < 8; ++i) {
            int idx = tid + i * 256;               // 0..2047
            int t2 = idx >> 10, rem = idx & 1023;
            int kk = rem >> 4, b4 = rem & 15;
            float4 v = *(const float4*)&g_hin[((size_t)(t0 + t2) * Hz + kc + kk) * Bz + b4 * 4];
            v.x = tf32r(v.x); v.y = tf32r(v.y); v.z = tf32r(v.z); v.w = tf32r(v.w);
            *(float4*)&s_h[t2 * (64 * XG_SH_PITCH) + kk * XG_SH_PITCH + b4 * 4] = v;
        }
        __syncthreads();

#pragma unroll
        for (int kk = 0; kk < 8; ++kk) {
            unsigned A0[4], A1[4];
#pragma unroll
            for (int j = 0; j < 4; ++j) {
                int rowa = mg * 32 + ((j & 1) << 3) + g;
                int ka = kk * 8 + tg + ((j >> 1) << 2);
                A0[j] = __float_as_uint(s_w[rowa * XG_SW_PITCH + ka]);
                A1[j] = __float_as_uint(s_w[(rowa + 16) * XG_SW_PITCH + ka]);
            }
#pragma unroll
            for (int t2 = 0; t2 < 2; ++t2)
#pragma unroll
                for (int nt = 0; nt < 4; ++nt) {
                    int n = bg * 32 + nt * 8 + g;
                    const float* hb = s_h + t2 * (64 * XG_SH_PITCH);
                    unsigned b0 = __float_as_uint(hb[(kk * 8 + tg) * XG_SH_PITCH + n]);
                    unsigned b1 = __float_as_uint(hb[(kk * 8 + tg + 4) * XG_SH_PITCH + n]);
                    mma8(acc[t2][0][nt], A0, b0, b1);
                    mma8(acc[t2][1][nt], A1, b0, b1);
                }
        }
        __syncthreads();
    }

#pragma unroll
    for (int mt = 0; mt < 2; ++mt) {
        int row = g0 + mg * 32 + mt * 16 + g;
        float bs0 = bih[row] + bhh[row];
        float bs1 = bih[row + 8] + bhh[row + 8];
#pragma unroll
        for (int t2 = 0; t2 < 2; ++t2)
#pragma unroll
            for (int nt = 0; nt < 4; ++nt) {
                int col = bg * 32 + nt * 8 + 2 * tg;
                size_t base = ((size_t)(t0 + t2) * Z4z + row) * Bz + col;
                float2 v0 = make_float2(acc[t2][mt][nt][0] + bs0, acc[t2][mt][nt][1] + bs0);
                *(float2*)&g_xg[base] = v0;
                float2 v1 = make_float2(acc[t2][mt][nt][2] + bs1, acc[t2][mt][nt][3] + bs1);
                *(float2*)&g_xg[base + (size_t)8 * Bz] = v1;
            }
    }
}

// --------------------------- reset barrier + h ------------------------------
__global__ void k_reset() {
    int i = blockIdx.x * blockDim.x + threadIdx.x;
    if (i == 0) g_barrier = 0u;
    if (i < Hz * Bz) { g_hbuf[0][i] = 0.f; g_hbuf[1][i] = 0.f; }
}

// --------------------------- persistent LSTM recurrence ---------------------
// 64 blocks x 256 threads.  Block owns 8 units (32 gate rows) x 64 batch.
// 8 warps = 8 K-slices of 64; stationary w_hh fragments in registers.
// h-exchange software-pipelined with MMA over 4 batch-chunks of 16.
#define RC_SH_PITCH 72
#define RC_SP_PITCH 72
#define RC_SH_FLTS  (Hz * RC_SH_PITCH)              // 36864
#define RC_SP_FLTS  (8 * 32 * RC_SP_PITCH)          // 18432
#define SMEM_RECUR  ((RC_SH_FLTS + RC_SP_FLTS) * 4) // 221184

__global__ void __launch_bounds__(256, 1) k_recur(const float* __restrict__ whh,
                                                  int phase) {
    const float* xg = phase ? g_xgdec : g_xg;
    const size_t tstr = phase ? 0 : (size_t)Z4z * Bz;
    float* hs = phase ? g_hs : (float*)0;

    extern __shared__ float sm[];
    float* s_h = sm;                    // [512][72]
    float* s_p = sm + RC_SH_FLTS;       // [8 ks][32 r][72]

    const int tid = threadIdx.x, bid = blockIdx.x;
    const int ks = tid >> 5, lane = tid & 31;
    const int g = lane >> 2, tg = lane & 3;

    // preload stationary A fragments (w_hh slice, tf32-rounded once)
    unsigned Af[2][8][4];
#pragma unroll
    for (int mt = 0; mt < 2; ++mt)
#pragma unroll
        for (int kk = 0; kk < 8; ++kk)
#pragma unroll
            for (int j = 0; j < 4; ++j) {
                int r = mt * 16 + ((j & 1) << 3) + g;
                int k = ks * 64 + kk * 8 + tg + ((j >> 1) << 2);
                int gate = r >> 3, ui = r & 7;
                int grow = gate * Hz + bid * 8 + ui;
                Af[mt][kk][j] = __float_as_uint(tf32r(whh[(size_t)grow * Hz + k]));
            }

    // cell-update mapping: warp = unit, lane = 2 consecutive batch
    const int ui = tid >> 5, b2 = (tid & 31) * 2;
    const int u_glob = bid * 8 + ui;
    float c0 = 0.f, c1 = 0.f;
    float2 xa[4];
    __syncthreads();

    for (int t = 0; t < Tz; ++t) {
        // gate preactivations (t-invariant in decoder phase: load once)
        if (t == 0 || tstr != 0) {
            const float* xp = xg + (size_t)t * tstr;
#pragma unroll
            for (int gt = 0; gt < 4; ++gt)
                xa[gt] = __ldg((const float2*)&xp[(gt * Hz + u_glob) * Bz + b2]);
        }

        float acc[2][8][4];
#pragma unroll
        for (int a = 0; a < 2; ++a)
#pragma unroll
            for (int b = 0; b < 8; ++b)
#pragma unroll
                for (int c = 0; c < 4; ++c) acc[a][b][c] = 0.f;

        // ---- pipelined h-exchange + mma over 4 batch-chunks of 16 cols ----
        const float4* src = (const float4*)g_hbuf[t & 1];
        float4 P[8];
        // prefetch chunk 0: g_hbuf row k (16 float4), chunk floats [0,16)
#pragma unroll
        for (int i = 0; i < 8; ++i) {
            int idx = tid + (i << 8);              // 0..2047
            int k = idx >> 2, b4 = idx & 3;
            P[i] = __ldcg(&src[k * 16 + b4]);
        }
#pragma unroll
        for (int c = 0; c < 4; ++c) {
            // commit chunk c to SMEM
#pragma unroll
            for (int i = 0; i < 8; ++i) {
                int idx = tid + (i << 8);
                int k = idx >> 2, b4 = idx & 3;
                *(float4*)&s_h[k * RC_SH_PITCH + c * 16 + b4 * 4] = P[i];
            }
            // prefetch chunk c+1 (overlaps with mma below)
            if (c < 3) {
#pragma unroll
                for (int i = 0; i < 8; ++i) {
                    int idx = tid + (i << 8);
                    int k = idx >> 2, b4 = idx & 3;
                    P[i] = __ldcg(&src[k * 16 + (c + 1) * 4 + b4]);
                }
            }
            __syncthreads();
            // mma on chunk c: n-tiles 2c, 2c+1 over this warp's K-slice
#pragma unroll
            for (int nn = 0; nn < 2; ++nn) {
                int nt = c * 2 + nn;
#pragma unroll
                for (int kk = 0; kk < 8; ++kk) {
                    int kr = ks * 64 + kk * 8;
                    unsigned b0 = __float_as_uint(s_h[(kr + tg) * RC_SH_PITCH + nt * 8 + g]);
                    unsigned b1 = __float_as_uint(s_h[(kr + tg + 4) * RC_SH_PITCH + nt * 8 + g]);
                    mma8(acc[0][nt], Af[0][kk], b0, b1);
                    mma8(acc[1][nt], Af[1][kk], b0, b1);
                }
            }
        }

        // store partials (float2)
#pragma unroll
        for (int mt = 0; mt < 2; ++mt)
#pragma unroll
            for (int nt = 0; nt < 8; ++nt) {
                int r = mt * 16 + g, b = nt * 8 + 2 * tg;
                float* p = s_p + ks * (32 * RC_SP_PITCH) + r * RC_SP_PITCH + b;
                *(float2*)&p[0] = make_float2(acc[mt][nt][0], acc[mt][nt][1]);
                *(float2*)&p[8 * RC_SP_PITCH] = make_float2(acc[mt][nt][2], acc[mt][nt][3]);
            }
        __syncthreads();

        // reduce K-slices + nonlinearity + cell update (2 consecutive batch)
        {
            float2 gs[4];
#pragma unroll
            for (int gt = 0; gt < 4; ++gt) {
                int r = gt * 8 + ui;
                float2 s = xa[gt];
#pragma unroll
                for (int k2 = 0; k2 < 8; ++k2) {
                    float2 v = *(const float2*)&s_p[k2 * (32 * RC_SP_PITCH) + r * RC_SP_PITCH + b2];
                    s.x += v.x; s.y += v.y;
                }
                gs[gt] = s;
            }
            float ivx = sigf(gs[0].x), fvx = sigf(gs[1].x), gvx = tanhf(gs[2].x), ovx = sigf(gs[3].x);
            float ivy = sigf(gs[0].y), fvy = sigf(gs[1].y), gvy = tanhf(gs[2].y), ovy = sigf(gs[3].y);
            c0 = fvx * c0 + ivx * gvx;
            c1 = fvy * c1 + ivy * gvy;
            float2 hv = make_float2(ovx * tanhf(c0), ovy * tanhf(c1));
            __stcg((float2*)&g_hbuf[(t + 1) & 1][u_glob * Bz + b2], hv);
            if (hs) *(float2*)&hs[((size_t)t * Hz + u_glob) * Bz + b2] = hv;
        }

        // CG-style grid barrier: bar -> release-arrive -> acquire-poll -> bar
        __syncthreads();
        if (tid == 0) {
            asm volatile("red.release.gpu.global.add.u32 [%0], 1;"
                         :: "l"(&g_barrier) : "memory");
            unsigned tgt = (unsigned)(t + 1) * gridDim.x;
            unsigned v;
            do {
                asm volatile("ld.acquire.gpu.global.u32 %0, [%1];"
                             : "=r"(v) : "l"(&g_barrier) : "memory");
            } while (v < tgt);
        }
        __syncthreads();
    }
}

// ------------------- mu / logvar / z (reads g_hbuf[0]) ---------------------
__global__ void k_latent(const float* __restrict__ muw, const float* __restrict__ mub,
                         const float* __restrict__ lvw, const float* __restrict__ lvb,
                         const float* __restrict__ eps, float* __restrict__ out) {
    int b = blockIdx.x, l = threadIdx.x;        // 64 blocks x 128 threads
    __shared__ float s_h[Hz];
    for (int k = l; k < Hz; k += 128) s_h[k] = g_hbuf[0][k * Bz + b];
    __syncthreads();
    float m = mub[l], v = lvb[l];
    for (int k = 0; k < Hz; ++k) {
        float h = s_h[k];
        m += muw[l * Hz + k] * h;
        v += lvw[l * Hz + k] * h;
    }
    out[512000 + b * LATz + l] = m;
    out[520192 + b * LATz + l] = v;
    g_z[b * LATz + l] = m + eps[b * LATz + l] * __expf(0.5f * v);
}

// --------------------------- d = z @ dec_in_wT + b -------------------------
__global__ void k_d(const float* __restrict__ w, const float* __restrict__ bias) {
    int b = blockIdx.x, h = threadIdx.x;        // 64 x 512
    __shared__ float s_z[LATz];
    if (h < LATz) s_z[h] = g_z[b * LATz + h];
    __syncthreads();
    float a = bias[h];
#pragma unroll 4
    for (int l = 0; l < LATz; ++l) a += w[h * LATz + l] * s_z[l];
    g_d[b * Hz + h] = a;
}

// ------------------- decoder gate preacts (constant over t) ----------------
__global__ void k_xgdec(const float* __restrict__ wih, const float* __restrict__ bih,
                        const float* __restrict__ bhh) {
    int b = blockIdx.x, gc = blockIdx.y;
    int g = gc * 512 + threadIdx.x;
    __shared__ float s_d[Hz];
    s_d[threadIdx.x] = g_d[b * Hz + threadIdx.x];
    __syncthreads();
    float a = bih[g] + bhh[g];
#pragma unroll 4
    for (int k = 0; k < Hz; ++k) a += wih[(size_t)g * Hz + k] * s_d[k];
    g_xgdec[g * Bz + b] = a;
}

// --------------------------- output projection -----------------------------
__global__ void __launch_bounds__(512) k_out(const float* __restrict__ w,
                                             const float* __restrict__ bias,
                                             float* __restrict__ out) {
    int t = blockIdx.x;
    __shared__ float s_w[8 * 520];
    __shared__ float s_h[64 * 64];
    int tid = threadIdx.x;
    for (int i = tid; i < INz * Hz; i += 512) s_w[(i >> 9) * 520 + (i & 511)] = w[i];
    int b = tid >> 3, o = tid & 7;
    float acc = bias[o];
    for (int kc = 0; kc < Hz; kc += 64) {
        __syncthreads();
        for (int i = tid; i < 1024; i += 512)
            *(float4*)&s_h[i * 4] = *(const float4*)&g_hs[((size_t)t * Hz + kc) * Bz + i * 4];
        __syncthreads();
#pragma unroll
        for (int kk = 0; kk < 64; ++kk) acc += s_h[kk * 64 + b] * s_w[o * 520 + kc + kk];
    }
    out[((size_t)b * Tz + t) * INz + o] = acc;
}

// ---------------------------------------------------------------------------
extern "C" void kernel_launch(void* const* d_in, const int* in_sizes, int n_in,
                              void* d_out, int out_size) {
    const float* x        = (const float*)d_in[0];
    const float* eps      = (const float*)d_in[1];
    const float* fcin_w   = (const float*)d_in[2];
    const float* fcin_b   = (const float*)d_in[3];
    const float* enc_wih  = (const float*)d_in[4];
    const float* enc_whh  = (const float*)d_in[5];
    const float* enc_bih  = (const float*)d_in[6];
    const float* enc_bhh  = (const float*)d_in[7];
    const float* mu_w     = (const float*)d_in[8];
    const float* mu_b     = (const float*)d_in[9];
    const float* lv_w     = (const float*)d_in[10];
    const float* lv_b     = (const float*)d_in[11];
    const float* din_w    = (const float*)d_in[12];
    const float* din_b    = (const float*)d_in[13];
    const float* dec_wih  = (const float*)d_in[14];
    const float* dec_whh  = (const float*)d_in[15];
    const float* dec_bih  = (const float*)d_in[16];
    const float* dec_bhh  = (const float*)d_in[17];
    const float* out_w    = (const float*)d_in[18];
    const float* out_b    = (const float*)d_in[19];
    float* out = (float*)d_out;

    cudaFuncSetAttribute(k_recur, cudaFuncAttributeMaxDynamicSharedMemorySize, SMEM_RECUR);
    cudaFuncSetAttribute(k_xg, cudaFuncAttributeMaxDynamicSharedMemorySize, SMEM_XG);

    k_ema<<<1, 512>>>(x);                                         // #1 (also resets)
    k_hin<<<dim3(Tz, Hz / 64), 256>>>(x, fcin_w, fcin_b);         // #2
    k_xg<<<dim3(Tz / 2, Z4z / 128), 256, SMEM_XG>>>(enc_wih, enc_bih, enc_bhh); // #3
    k_recur<<<64, 256, SMEM_RECUR>>>(enc_whh, 0);                 // #4 <- ncu capture
    k_latent<<<Bz, LATz>>>(mu_w, mu_b, lv_w, lv_b, eps, out);
    k_d<<<Bz, Hz>>>(din_w, din_b);
    k_xgdec<<<dim3(Bz, 4), 512>>>(dec_wih, dec_bih, dec_bhh);
    k_reset<<<129, 256>>>();
    k_recur<<<64, 256, SMEM_RECUR>>>(dec_whh, 1);
    k_out<<<Tz, 512>>>(out_w, out_b, out);
}

// round 14
// speedup vs baseline: 1.4665x; 1.4665x over previous
#include <cuda_runtime.h>
#include <cuda_fp16.h>
#include <cuda_bf16.h>

// ---------------------------------------------------------------------------
// LSTM-VAE forward.  B=64, T=1000, IN=8, H=512, Z4=2048, LAT=128
// xg projection: tf32 mma (m16n8k8).  Recurrence: fp16 mma (m16n8k16),
// fp32 accumulate, persistent grid, CG-style barrier.
// Output layout: [recon (B,T,IN) | mu (B,LAT) | logvar (B,LAT)]
// ---------------------------------------------------------------------------

#define Bz   64
#define Tz   1000
#define INz  8
#define Hz   512
#define Z4z  2048
#define LATz 128

// ------------------------- scratch (__device__ globals) --------------------
__device__ float  g_e[Bz * Tz];                      // EMA channel      (B,T)
__device__ float  g_hin[(size_t)Tz * Hz * Bz];       // enc input        (T,H,B)
__device__ float  g_xg[(size_t)Tz * Z4z * Bz];       // enc gate preacts (T,Z4,B)
__device__ float  g_xgdec[Z4z * Bz];                 // dec gate preacts (Z4,B)
__device__ __half g_hbuf[2][Bz * Hz];                // h double buffer  ([b][k], fp16)
__device__ float  g_hs[(size_t)Tz * Hz * Bz];        // dec hidden seq   (T,H,B)
__device__ float  g_z[Bz * LATz];
__device__ float  g_d[Bz * Hz];
__device__ unsigned g_barrier;

__device__ __forceinline__ float sigf(float x) { return 1.f / (1.f + __expf(-x)); }

// mma helpers ----------------------------------------------------------------
__device__ __forceinline__ float tf32r(float f) {
    unsigned u;
    asm("cvt.rna.tf32.f32 %0, %1;" : "=r"(u) : "f"(f));
    return __uint_as_float(u);
}
__device__ __forceinline__ void mma8(float* d, const unsigned* a, unsigned b0, unsigned b1) {
    asm volatile(
        "mma.sync.aligned.m16n8k8.row.col.f32.tf32.tf32.f32 "
        "{%0,%1,%2,%3},{%4,%5,%6,%7},{%8,%9},{%0,%1,%2,%3};"
        : "+f"(d[0]), "+f"(d[1]), "+f"(d[2]), "+f"(d[3])
        : "r"(a[0]), "r"(a[1]), "r"(a[2]), "r"(a[3]), "r"(b0), "r"(b1));
}
__device__ __forceinline__ void mma16(float* d, const unsigned* a, unsigned b0, unsigned b1) {
    asm volatile(
        "mma.sync.aligned.m16n8k16.row.col.f32.f16.f16.f32 "
        "{%0,%1,%2,%3},{%4,%5,%6,%7},{%8,%9},{%0,%1,%2,%3};"
        : "+f"(d[0]), "+f"(d[1]), "+f"(d[2]), "+f"(d[3])
        : "r"(a[0]), "r"(a[1]), "r"(a[2]), "r"(a[3]), "r"(b0), "r"(b1));
}
__device__ __forceinline__ unsigned packh2(float a, float b) {
    __half2 p = __floats2half2_rn(a, b);
    return *reinterpret_cast<unsigned*>(&p);
}

// ---------------------- EMA (parallel scan) + reset ------------------------
__global__ void k_ema(const float* __restrict__ x) {
    __shared__ float s_end[8 * 64];
    __shared__ float s_init[8 * 64];
    int tid = threadIdx.x, b = tid & 63, c = tid >> 6;

    // fused reset (h buffers are half)
    unsigned* hb0 = (unsigned*)g_hbuf[0];
    unsigned* hb1 = (unsigned*)g_hbuf[1];
    for (int i = tid; i < Bz * Hz / 2; i += 512) { hb0[i] = 0u; hb1[i] = 0u; }
    if (tid == 0) g_barrier = 0u;

    int t0 = c * 125;
    float e = 0.f;
    for (int i = 0; i < 125; ++i) {
        int t = t0 + i;
        float v = x[((size_t)b * Tz + t) * INz + 1];
        e = (c == 0 && i == 0) ? v : (0.1f * v + 0.9f * e);
        g_e[b * Tz + t] = e;
    }
    s_end[c * 64 + b] = e;
    __syncthreads();
    if (tid < 64) {
        const float P125 = 1.906849e-6f;       // 0.9^125
        float E = s_end[0 * 64 + tid];         // chunk0 is exact
        for (int cc = 1; cc < 8; ++cc) {
            s_init[cc * 64 + tid] = E;
            E = s_end[cc * 64 + tid] + E * P125;
        }
    }
    __syncthreads();
    if (c >= 1) {
        float I = s_init[c * 64 + b];
        float pw = 0.9f;
        for (int i = 0; i < 125; ++i) {
            g_e[b * Tz + t0 + i] += I * pw;
            pw *= 0.9f;
        }
    }
}

// ---------------- input FC + ReLU + positional encoding --------------------
__global__ void __launch_bounds__(256) k_hin(const float* __restrict__ x,
                                             const float* __restrict__ w,
                                             const float* __restrict__ bias) {
    int t = blockIdx.x, ht = blockIdx.y * 64;
    __shared__ float s_x[64][8];
    __shared__ float s_w[64][8];
    __shared__ float s_b[64];
    __shared__ float s_pe[64];
    int tid = threadIdx.x;

    for (int i = tid; i < 512; i += 256) {
        int bb = i >> 3, ii = i & 7;
        float v = x[((size_t)bb * Tz + t) * INz + ii];
        if (ii == 1) v = g_e[bb * Tz + t];
        s_x[bb][ii] = v;
    }
    for (int i = tid; i < 512; i += 256) {
        int hh = i >> 3, ii = i & 7;
        s_w[hh][ii] = w[(ht + hh) * INz + ii];
    }
    if (tid < 64) {
        int h = ht + tid;
        s_b[tid] = bias[h];
        int j = h >> 1;
        float div = __expf(-(float)(2 * j) * (9.2103403719761836f / 512.f));
        float ang = (float)t * div;
        s_pe[tid] = 0.1f * ((h & 1) ? cosf(ang) : sinf(ang));
    }
    __syncthreads();

    int hh = tid >> 2, bq = tid & 3;
    for (int q = 0; q < 16; ++q) {
        int bb = bq * 16 + q;
        float a = s_b[hh];
#pragma unroll
        for (int i = 0; i < 8; ++i) a += s_w[hh][i] * s_x[bb][i];
        a = fmaxf(a, 0.f) + s_pe[hh];
        g_hin[((size_t)t * Hz + ht + hh) * Bz + bb] = a;
    }
}

// ------------- encoder gate preactivations: xg = hin @ w_ihT + b -----------
#define XG_SW_PITCH 68
#define XG_SH_PITCH 72
#define SMEM_XG ((128 * XG_SW_PITCH + 2 * 64 * XG_SH_PITCH) * 4)

__global__ void __launch_bounds__(256) k_xg(const float* __restrict__ wih,
                                            const float* __restrict__ bih,
                                            const float* __restrict__ bhh) {
    extern __shared__ float sm[];
    float* s_w = sm;                               // [128][68]
    float* s_h = sm + 128 * XG_SW_PITCH;           // [2][64][72]

    const int t0 = blockIdx.x * 2, g0 = blockIdx.y * 128;
    const int tid = threadIdx.x;
    const int wid = tid >> 5, lane = tid & 31;
    const int mg = wid >> 1, bg = wid & 1;
    const int g = lane >> 2, tg = lane & 3;

    float acc[2][2][4][4];
#pragma unroll
    for (int a = 0; a < 2; ++a)
#pragma unroll
        for (int b = 0; b < 2; ++b)
#pragma unroll
            for (int c = 0; c < 4; ++c)
#pragma unroll
                for (int d = 0; d < 4; ++d) acc[a][b][c][d] = 0.f;

    for (int kc = 0; kc < Hz; kc += 64) {
#pragma unroll
        for (int i = 0; i < 8; ++i) {
            int idx = tid + i * 256;               // 0..2047
            int r = idx >> 4, k4 = idx & 15;
            float4 v = *(const float4*)&wih[(size_t)(g0 + r) * Hz + kc + k4 * 4];
            v.x = tf32r(v.x); v.y = tf32r(v.y); v.z = tf32r(v.z); v.w = tf32r(v.w);
            *(float4*)&s_w[r * XG_SW_PITCH + k4 * 4] = v;
        }
#pragma unroll
        for (int i = 0; i < 8; ++i) {
            int idx = tid + i * 256;               // 0..2047
            int t2 = idx >> 10, rem = idx & 1023;
            int kk = rem >> 4, b4 = rem & 15;
            float4 v = *(const float4*)&g_hin[((size_t)(t0 + t2) * Hz + kc + kk) * Bz + b4 * 4];
            v.x = tf32r(v.x); v.y = tf32r(v.y); v.z = tf32r(v.z); v.w = tf32r(v.w);
            *(float4*)&s_h[t2 * (64 * XG_SH_PITCH) + kk * XG_SH_PITCH + b4 * 4] = v;
        }
        __syncthreads();

#pragma unroll
        for (int kk = 0; kk < 8; ++kk) {
            unsigned A0[4], A1[4];
#pragma unroll
            for (int j = 0; j < 4; ++j) {
                int rowa = mg * 32 + ((j & 1) << 3) + g;
                int ka = kk * 8 + tg + ((j >> 1) << 2);
                A0[j] = __float_as_uint(s_w[rowa * XG_SW_PITCH + ka]);
                A1[j] = __float_as_uint(s_w[(rowa + 16) * XG_SW_PITCH + ka]);
            }
#pragma unroll
            for (int t2 = 0; t2 < 2; ++t2)
#pragma unroll
                for (int nt = 0; nt < 4; ++nt) {
                    int n = bg * 32 + nt * 8 + g;
                    const float* hb = s_h + t2 * (64 * XG_SH_PITCH);
                    unsigned b0 = __float_as_uint(hb[(kk * 8 + tg) * XG_SH_PITCH + n]);
                    unsigned b1 = __float_as_uint(hb[(kk * 8 + tg + 4) * XG_SH_PITCH + n]);
                    mma8(acc[t2][0][nt], A0, b0, b1);
                    mma8(acc[t2][1][nt], A1, b0, b1);
                }
        }
        __syncthreads();
    }

#pragma unroll
    for (int mt = 0; mt < 2; ++mt) {
        int row = g0 + mg * 32 + mt * 16 + g;
        float bs0 = bih[row] + bhh[row];
        float bs1 = bih[row + 8] + bhh[row + 8];
#pragma unroll
        for (int t2 = 0; t2 < 2; ++t2)
#pragma unroll
            for (int nt = 0; nt < 4; ++nt) {
                int col = bg * 32 + nt * 8 + 2 * tg;
                size_t base = ((size_t)(t0 + t2) * Z4z + row) * Bz + col;
                float2 v0 = make_float2(acc[t2][mt][nt][0] + bs0, acc[t2][mt][nt][1] + bs0);
                *(float2*)&g_xg[base] = v0;
                float2 v1 = make_float2(acc[t2][mt][nt][2] + bs1, acc[t2][mt][nt][3] + bs1);
                *(float2*)&g_xg[base + (size_t)8 * Bz] = v1;
            }
    }
}

// --------------------------- reset barrier + h ------------------------------
__global__ void k_reset() {
    int i = blockIdx.x * blockDim.x + threadIdx.x;
    if (i == 0) g_barrier = 0u;
    if (i < Bz * Hz / 2) {
        ((unsigned*)g_hbuf[0])[i] = 0u;
        ((unsigned*)g_hbuf[1])[i] = 0u;
    }
}

// --------------------------- persistent LSTM recurrence ---------------------
// 64 blocks x 256 threads.  Block owns 8 units (32 gate rows) x 64 batch.
// 8 warps = 8 K-slices of 64; stationary w_hh fp16 fragments in registers.
// fp16 mma m16n8k16, fp32 accumulate.  h stored [batch][hidden] in fp16.
#define RC_SH_PITCH 520                              // halves per batch row
#define RC_SP_PITCH 72
#define RC_SH_BYTES (Bz * RC_SH_PITCH * 2)           // 66560
#define RC_SP_BYTES (8 * 32 * RC_SP_PITCH * 4)       // 73728
#define RC_ST_BYTES (Bz * 8 * 2)                     // 1024
#define SMEM_RECUR  (RC_SH_BYTES + RC_SP_BYTES + RC_ST_BYTES)

__global__ void __launch_bounds__(256, 1) k_recur(const float* __restrict__ whh,
                                                  int phase) {
    const float* xg = phase ? g_xgdec : g_xg;
    const size_t tstr = phase ? 0 : (size_t)Z4z * Bz;
    float* hs = phase ? g_hs : (float*)0;

    extern __shared__ char smc[];
    __half* s_h = (__half*)smc;                            // [64][520]
    float*  s_p = (float*)(smc + RC_SH_BYTES);             // [8 ks][32 r][72]
    __half* s_t = (__half*)(smc + RC_SH_BYTES + RC_SP_BYTES); // [64][8]

    const int tid = threadIdx.x, bid = blockIdx.x;
    const int ks = tid >> 5, lane = tid & 31;
    const int g = lane >> 2, tg = lane & 3;

    // preload stationary A fragments (w_hh slice, fp16 pairs along k)
    // local row r = gate*8 + ui -> global gate row = gate*512 + bid*8 + ui
    unsigned Af[2][4][4];
#pragma unroll
    for (int mt = 0; mt < 2; ++mt)
#pragma unroll
        for (int kk = 0; kk < 4; ++kk)
#pragma unroll
            for (int j = 0; j < 4; ++j) {
                int r = mt * 16 + ((j & 1) << 3) + g;
                int k0 = ks * 64 + kk * 16 + 2 * tg + ((j >> 1) << 3);
                int gate = r >> 3, ui = r & 7;
                int grow = gate * Hz + bid * 8 + ui;
                Af[mt][kk][j] = packh2(whh[(size_t)grow * Hz + k0],
                                       whh[(size_t)grow * Hz + k0 + 1]);
            }

    // cell-update mapping: warp = unit, lane = 2 consecutive batch
    const int ui = tid >> 5, b2 = (tid & 31) * 2;
    const int u_glob = bid * 8 + ui;
    float c0 = 0.f, c1 = 0.f;
    float2 xa[4];
    __syncthreads();

    for (int t = 0; t < Tz; ++t) {
        // gate preactivations (t-invariant in decoder phase: load once)
        if (t == 0 || tstr != 0) {
            const float* xp = xg + (size_t)t * tstr;
#pragma unroll
            for (int gt = 0; gt < 4; ++gt)
                xa[gt] = __ldg((const float2*)&xp[(gt * Hz + u_glob) * Bz + b2]);
        }

        // stage h_{t-1} (L2 -> SMEM): 64KB as 4096 x 16B, [b][k] layout
        {
            const uint4* src = (const uint4*)g_hbuf[t & 1];
#pragma unroll
            for (int i = 0; i < 16; ++i) {
                int idx = tid + (i << 8);          // 0..4095
                int b = idx >> 6, kq = idx & 63;   // kq: 8-half group
                uint4 v = __ldcg(&src[idx]);
                *(uint4*)&s_h[b * RC_SH_PITCH + kq * 8] = v;
            }
        }
        __syncthreads();

        // mma: 2 m-tiles x 8 n-tiles x 4 k16-steps over this warp's K-slice
        float acc[2][8][4];
#pragma unroll
        for (int a = 0; a < 2; ++a)
#pragma unroll
            for (int b = 0; b < 8; ++b)
#pragma unroll
                for (int c = 0; c < 4; ++c) acc[a][b][c] = 0.f;

#pragma unroll
        for (int nt = 0; nt < 8; ++nt) {
            const __half* hrow = s_h + (nt * 8 + g) * RC_SH_PITCH;
#pragma unroll
            for (int kk = 0; kk < 4; ++kk) {
                int k0 = ks * 64 + kk * 16 + 2 * tg;
                unsigned b0 = *(const unsigned*)&hrow[k0];
                unsigned b1 = *(const unsigned*)&hrow[k0 + 8];
                mma16(acc[0][nt], Af[0][kk], b0, b1);
                mma16(acc[1][nt], Af[1][kk], b0, b1);
            }
        }

        // store partials (float2)
#pragma unroll
        for (int mt = 0; mt < 2; ++mt)
#pragma unroll
            for (int nt = 0; nt < 8; ++nt) {
                int r = mt * 16 + g, b = nt * 8 + 2 * tg;
                float* p = s_p + ks * (32 * RC_SP_PITCH) + r * RC_SP_PITCH + b;
                *(float2*)&p[0] = make_float2(acc[mt][nt][0], acc[mt][nt][1]);
                *(float2*)&p[8 * RC_SP_PITCH] = make_float2(acc[mt][nt][2], acc[mt][nt][3]);
            }
        __syncthreads();

        // reduce K-slices + nonlinearity + cell update (2 consecutive batch)
        {
            float2 gs[4];
#pragma unroll
            for (int gt = 0; gt < 4; ++gt) {
                int r = gt * 8 + ui;
                float2 s = xa[gt];
#pragma unroll
                for (int k2 = 0; k2 < 8; ++k2) {
                    float2 v = *(const float2*)&s_p[k2 * (32 * RC_SP_PITCH) + r * RC_SP_PITCH + b2];
                    s.x += v.x; s.y += v.y;
                }
                gs[gt] = s;
            }
            float ivx = sigf(gs[0].x), fvx = sigf(gs[1].x), gvx = tanhf(gs[2].x), ovx = sigf(gs[3].x);
            float ivy = sigf(gs[0].y), fvy = sigf(gs[1].y), gvy = tanhf(gs[2].y), ovy = sigf(gs[3].y);
            c0 = fvx * c0 + ivx * gvx;
            c1 = fvy * c1 + ivy * gvy;
            float hx = ovx * tanhf(c0), hy = ovy * tanhf(c1);
            // transpose through SMEM for coalesced [b][k] half stores
            s_t[b2 * 8 + ui]       = __float2half_rn(hx);
            s_t[(b2 + 1) * 8 + ui] = __float2half_rn(hy);
            if (hs) *(float2*)&hs[((size_t)t * Hz + u_glob) * Bz + b2] = make_float2(hx, hy);
        }
        __syncthreads();
        if (tid < 64) {
            uint4 v = *(const uint4*)&s_t[tid * 8];    // 8 halves = this b's 8 units
            __stcg((uint4*)&g_hbuf[(t + 1) & 1][tid * Hz + bid * 8], v);
        }

        // CG-style grid barrier: bar -> release-arrive -> acquire-poll -> bar
        __syncthreads();
        if (tid == 0) {
            asm volatile("red.release.gpu.global.add.u32 [%0], 1;"
                         :: "l"(&g_barrier) : "memory");
            unsigned tgt = (unsigned)(t + 1) * gridDim.x;
            unsigned v;
            do {
                asm volatile("ld.acquire.gpu.global.u32 %0, [%1];"
                             : "=r"(v) : "l"(&g_barrier) : "memory");
            } while (v < tgt);
        }
        __syncthreads();
    }
}

// ------------------- mu / logvar / z (reads g_hbuf[0], [b][k] fp16) --------
__global__ void k_latent(const float* __restrict__ muw, const float* __restrict__ mub,
                         const float* __restrict__ lvw, const float* __restrict__ lvb,
                         const float* __restrict__ eps, float* __restrict__ out) {
    int b = blockIdx.x, l = threadIdx.x;        // 64 blocks x 128 threads
    __shared__ float s_h[Hz];
    for (int k = l; k < Hz; k += 128) s_h[k] = __half2float(g_hbuf[0][b * Hz + k]);
    __syncthreads();
    float m = mub[l], v = lvb[l];
    for (int k = 0; k < Hz; ++k) {
        float h = s_h[k];
        m += muw[l * Hz + k] * h;
        v += lvw[l * Hz + k] * h;
    }
    out[512000 + b * LATz + l] = m;
    out[520192 + b * LATz + l] = v;
    g_z[b * LATz + l] = m + eps[b * LATz + l] * __expf(0.5f * v);
}

// --------------------------- d = z @ dec_in_wT + b -------------------------
__global__ void k_d(const float* __restrict__ w, const float* __restrict__ bias) {
    int b = blockIdx.x, h = threadIdx.x;        // 64 x 512
    __shared__ float s_z[LATz];
    if (h < LATz) s_z[h] = g_z[b * LATz + h];
    __syncthreads();
    float a = bias[h];
#pragma unroll 4
    for (int l = 0; l < LATz; ++l) a += w[h * LATz + l] * s_z[l];
    g_d[b * Hz + h] = a;
}

// ------------------- decoder gate preacts (constant over t) ----------------
__global__ void k_xgdec(const float* __restrict__ wih, const float* __restrict__ bih,
                        const float* __restrict__ bhh) {
    int b = blockIdx.x, gc = blockIdx.y;
    int g = gc * 512 + threadIdx.x;
    __shared__ float s_d[Hz];
    s_d[threadIdx.x] = g_d[b * Hz + threadIdx.x];
    __syncthreads();
    float a = bih[g] + bhh[g];
#pragma unroll 4
    for (int k = 0; k < Hz; ++k) a += wih[(size_t)g * Hz + k] * s_d[k];
    g_xgdec[g * Bz + b] = a;
}

// --------------------------- output projection -----------------------------
__global__ void __launch_bounds__(512) k_out(const float* __restrict__ w,
                                             const float* __restrict__ bias,
                                             float* __restrict__ out) {
    int t = blockIdx.x;
    __shared__ float s_w[8 * 520];
    __shared__ float s_h[64 * 64];
    int tid = threadIdx.x;
    for (int i = tid; i < INz * Hz; i += 512) s_w[(i >> 9) * 520 + (i & 511)] = w[i];
    int b = tid >> 3, o = tid & 7;
    float acc = bias[o];
    for (int kc = 0; kc < Hz; kc += 64) {
        __syncthreads();
        for (int i = tid; i < 1024; i += 512)
            *(float4*)&s_h[i * 4] = *(const float4*)&g_hs[((size_t)t * Hz + kc) * Bz + i * 4];
        __syncthreads();
#pragma unroll
        for (int kk = 0; kk < 64; ++kk) acc += s_h[kk * 64 + b] * s_w[o * 520 + kc + kk];
    }
    out[((size_t)b * Tz + t) * INz + o] = acc;
}

// ---------------------------------------------------------------------------
extern "C" void kernel_launch(void* const* d_in, const int* in_sizes, int n_in,
                              void* d_out, int out_size) {
    const float* x        = (const float*)d_in[0];
    const float* eps      = (const float*)d_in[1];
    const float* fcin_w   = (const float*)d_in[2];
    const float* fcin_b   = (const float*)d_in[3];
    const float* enc_wih  = (const float*)d_in[4];
    const float* enc_whh  = (const float*)d_in[5];
    const float* enc_bih  = (const float*)d_in[6];
    const float* enc_bhh  = (const float*)d_in[7];
    const float* mu_w     = (const float*)d_in[8];
    const float* mu_b     = (const float*)d_in[9];
    const float* lv_w     = (const float*)d_in[10];
    const float* lv_b     = (const float*)d_in[11];
    const float* din_w    = (const float*)d_in[12];
    const float* din_b    = (const float*)d_in[13];
    const float* dec_wih  = (const float*)d_in[14];
    const float* dec_whh  = (const float*)d_in[15];
    const float* dec_bih  = (const float*)d_in[16];
    const float* dec_bhh  = (const float*)d_in[17];
    const float* out_w    = (const float*)d_in[18];
    const float* out_b    = (const float*)d_in[19];
    float* out = (float*)d_out;

    cudaFuncSetAttribute(k_recur, cudaFuncAttributeMaxDynamicSharedMemorySize, SMEM_RECUR);
    cudaFuncSetAttribute(k_xg, cudaFuncAttributeMaxDynamicSharedMemorySize, SMEM_XG);

    k_ema<<<1, 512>>>(x);                                         // #1 (also resets)
    k_hin<<<dim3(Tz, Hz / 64), 256>>>(x, fcin_w, fcin_b);         // #2
    k_xg<<<dim3(Tz / 2, Z4z / 128), 256, SMEM_XG>>>(enc_wih, enc_bih, enc_bhh); // #3
    k_recur<<<64, 256, SMEM_RECUR>>>(enc_whh, 0);                 // #4 <- ncu capture
    k_latent<<<Bz, LATz>>>(mu_w, mu_b, lv_w, lv_b, eps, out);
    k_d<<<Bz, Hz>>>(din_w, din_b);
    k_xgdec<<<dim3(Bz, 4), 512>>>(dec_wih, dec_bih, dec_bhh);
    k_reset<<<129, 256>>>();
    k_recur<<<64, 256, SMEM_RECUR>>>(dec_whh, 1);
    k_out<<<Tz, 512>>>(out_w, out_b, out);
}

// round 15
// speedup vs baseline: 1.4788x; 1.0083x over previous
#include <cuda_runtime.h>
#include <cuda_fp16.h>
#include <cuda_bf16.h>

// ---------------------------------------------------------------------------
// LSTM-VAE forward.  B=64, T=1000, IN=8, H=512, Z4=2048, LAT=128
// xg projection: tf32 mma (m16n8k8).  Recurrence: fp16 mma (m16n8k16),
// fp32 accumulate, persistent grid, warp-autonomous staging, CG barrier.
// Output layout: [recon (B,T,IN) | mu (B,LAT) | logvar (B,LAT)]
// ---------------------------------------------------------------------------

#define Bz   64
#define Tz   1000
#define INz  8
#define Hz   512
#define Z4z  2048
#define LATz 128

// ------------------------- scratch (__device__ globals) --------------------
__device__ float  g_e[Bz * Tz];                      // EMA channel      (B,T)
__device__ float  g_hin[(size_t)Tz * Hz * Bz];       // enc input        (T,H,B)
__device__ float  g_xg[(size_t)Tz * Z4z * Bz];       // enc gate preacts (T,Z4,B)
__device__ float  g_xgdec[Z4z * Bz];                 // dec gate preacts (Z4,B)
__device__ __half g_hbuf[2][Bz * Hz];                // h double buffer  ([b][k], fp16)
__device__ float  g_hs[(size_t)Tz * Hz * Bz];        // dec hidden seq   (T,H,B)
__device__ float  g_z[Bz * LATz];
__device__ float  g_d[Bz * Hz];
__device__ unsigned g_barrier;

__device__ __forceinline__ float sigf(float x) { return 1.f / (1.f + __expf(-x)); }
__device__ __forceinline__ float tanhfast(float x) {
    float e = __expf(-2.f * fabsf(x));
    float r = (1.f - e) / (1.f + e);
    return copysignf(r, x);
}

// mma helpers ----------------------------------------------------------------
__device__ __forceinline__ float tf32r(float f) {
    unsigned u;
    asm("cvt.rna.tf32.f32 %0, %1;" : "=r"(u) : "f"(f));
    return __uint_as_float(u);
}
__device__ __forceinline__ void mma8(float* d, const unsigned* a, unsigned b0, unsigned b1) {
    asm volatile(
        "mma.sync.aligned.m16n8k8.row.col.f32.tf32.tf32.f32 "
        "{%0,%1,%2,%3},{%4,%5,%6,%7},{%8,%9},{%0,%1,%2,%3};"
        : "+f"(d[0]), "+f"(d[1]), "+f"(d[2]), "+f"(d[3])
        : "r"(a[0]), "r"(a[1]), "r"(a[2]), "r"(a[3]), "r"(b0), "r"(b1));
}
__device__ __forceinline__ void mma16(float* d, const unsigned* a, unsigned b0, unsigned b1) {
    asm volatile(
        "mma.sync.aligned.m16n8k16.row.col.f32.f16.f16.f32 "
        "{%0,%1,%2,%3},{%4,%5,%6,%7},{%8,%9},{%0,%1,%2,%3};"
        : "+f"(d[0]), "+f"(d[1]), "+f"(d[2]), "+f"(d[3])
        : "r"(a[0]), "r"(a[1]), "r"(a[2]), "r"(a[3]), "r"(b0), "r"(b1));
}
__device__ __forceinline__ unsigned packh2(float a, float b) {
    __half2 p = __floats2half2_rn(a, b);
    return *reinterpret_cast<unsigned*>(&p);
}

// ---------------------- EMA (parallel scan) + reset ------------------------
__global__ void k_ema(const float* __restrict__ x) {
    __shared__ float s_end[8 * 64];
    __shared__ float s_init[8 * 64];
    int tid = threadIdx.x, b = tid & 63, c = tid >> 6;

    // fused reset (h buffers are half)
    unsigned* hb0 = (unsigned*)g_hbuf[0];
    unsigned* hb1 = (unsigned*)g_hbuf[1];
    for (int i = tid; i < Bz * Hz / 2; i += 512) { hb0[i] = 0u; hb1[i] = 0u; }
    if (tid == 0) g_barrier = 0u;

    int t0 = c * 125;
    float e = 0.f;
    for (int i = 0; i < 125; ++i) {
        int t = t0 + i;
        float v = x[((size_t)b * Tz + t) * INz + 1];
        e = (c == 0 && i == 0) ? v : (0.1f * v + 0.9f * e);
        g_e[b * Tz + t] = e;
    }
    s_end[c * 64 + b] = e;
    __syncthreads();
    if (tid < 64) {
        const float P125 = 1.906849e-6f;       // 0.9^125
        float E = s_end[0 * 64 + tid];         // chunk0 is exact
        for (int cc = 1; cc < 8; ++cc) {
            s_init[cc * 64 + tid] = E;
            E = s_end[cc * 64 + tid] + E * P125;
        }
    }
    __syncthreads();
    if (c >= 1) {
        float I = s_init[c * 64 + b];
        float pw = 0.9f;
        for (int i = 0; i < 125; ++i) {
            g_e[b * Tz + t0 + i] += I * pw;
            pw *= 0.9f;
        }
    }
}

// ---------------- input FC + ReLU + positional encoding --------------------
__global__ void __launch_bounds__(256) k_hin(const float* __restrict__ x,
                                             const float* __restrict__ w,
                                             const float* __restrict__ bias) {
    int t = blockIdx.x, ht = blockIdx.y * 64;
    __shared__ float s_x[64][8];
    __shared__ float s_w[64][8];
    __shared__ float s_b[64];
    __shared__ float s_pe[64];
    int tid = threadIdx.x;

    for (int i = tid; i < 512; i += 256) {
        int bb = i >> 3, ii = i & 7;
        float v = x[((size_t)bb * Tz + t) * INz + ii];
        if (ii == 1) v = g_e[bb * Tz + t];
        s_x[bb][ii] = v;
    }
    for (int i = tid; i < 512; i += 256) {
        int hh = i >> 3, ii = i & 7;
        s_w[hh][ii] = w[(ht + hh) * INz + ii];
    }
    if (tid < 64) {
        int h = ht + tid;
        s_b[tid] = bias[h];
        int j = h >> 1;
        float div = __expf(-(float)(2 * j) * (9.2103403719761836f / 512.f));
        float ang = (float)t * div;
        s_pe[tid] = 0.1f * ((h & 1) ? cosf(ang) : sinf(ang));
    }
    __syncthreads();

    int hh = tid >> 2, bq = tid & 3;
    for (int q = 0; q < 16; ++q) {
        int bb = bq * 16 + q;
        float a = s_b[hh];
#pragma unroll
        for (int i = 0; i < 8; ++i) a += s_w[hh][i] * s_x[bb][i];
        a = fmaxf(a, 0.f) + s_pe[hh];
        g_hin[((size_t)t * Hz + ht + hh) * Bz + bb] = a;
    }
}

// ------------- encoder gate preactivations: xg = hin @ w_ihT + b -----------
#define XG_SW_PITCH 68
#define XG_SH_PITCH 72
#define SMEM_XG ((128 * XG_SW_PITCH + 2 * 64 * XG_SH_PITCH) * 4)

__global__ void __launch_bounds__(256) k_xg(const float* __restrict__ wih,
                                            const float* __restrict__ bih,
                                            const float* __restrict__ bhh) {
    extern __shared__ float sm[];
    float* s_w = sm;                               // [128][68]
    float* s_h = sm + 128 * XG_SW_PITCH;           // [2][64][72]

    const int t0 = blockIdx.x * 2, g0 = blockIdx.y * 128;
    const int tid = threadIdx.x;
    const int wid = tid >> 5, lane = tid & 31;
    const int mg = wid >> 1, bg = wid & 1;
    const int g = lane >> 2, tg = lane & 3;

    float acc[2][2][4][4];
#pragma unroll
    for (int a = 0; a < 2; ++a)
#pragma unroll
        for (int b = 0; b < 2; ++b)
#pragma unroll
            for (int c = 0; c < 4; ++c)
#pragma unroll
                for (int d = 0; d < 4; ++d) acc[a][b][c][d] = 0.f;

    for (int kc = 0; kc < Hz; kc += 64) {
#pragma unroll
        for (int i = 0; i < 8; ++i) {
            int idx = tid + i * 256;               // 0..2047
            int r = idx >> 4, k4 = idx & 15;
            float4 v = *(const float4*)&wih[(size_t)(g0 + r) * Hz + kc + k4 * 4];
            v.x = tf32r(v.x); v.y = tf32r(v.y); v.z = tf32r(v.z); v.w = tf32r(v.w);
            *(float4*)&s_w[r * XG_SW_PITCH + k4 * 4] = v;
        }
#pragma unroll
        for (int i = 0; i < 8; ++i) {
            int idx = tid + i * 256;               // 0..2047
            int t2 = idx >> 10, rem = idx & 1023;
            int kk = rem >> 4, b4 = rem & 15;
            float4 v = *(const float4*)&g_hin[((size_t)(t0 + t2) * Hz + kc + kk) * Bz + b4 * 4];
            v.x = tf32r(v.x); v.y = tf32r(v.y); v.z = tf32r(v.z); v.w = tf32r(v.w);
            *(float4*)&s_h[t2 * (64 * XG_SH_PITCH) + kk * XG_SH_PITCH + b4 * 4] = v;
        }
        __syncthreads();

#pragma unroll
        for (int kk = 0; kk < 8; ++kk) {
            unsigned A0[4], A1[4];
#pragma unroll
            for (int j = 0; j < 4; ++j) {
                int rowa = mg * 32 + ((j & 1) << 3) + g;
                int ka = kk * 8 + tg + ((j >> 1) << 2);
                A0[j] = __float_as_uint(s_w[rowa * XG_SW_PITCH + ka]);
                A1[j] = __float_as_uint(s_w[(rowa + 16) * XG_SW_PITCH + ka]);
            }
#pragma unroll
            for (int t2 = 0; t2 < 2; ++t2)
#pragma unroll
                for (int nt = 0; nt < 4; ++nt) {
                    int n = bg * 32 + nt * 8 + g;
                    const float* hb = s_h + t2 * (64 * XG_SH_PITCH);
                    unsigned b0 = __float_as_uint(hb[(kk * 8 + tg) * XG_SH_PITCH + n]);
                    unsigned b1 = __float_as_uint(hb[(kk * 8 + tg + 4) * XG_SH_PITCH + n]);
                    mma8(acc[t2][0][nt], A0, b0, b1);
                    mma8(acc[t2][1][nt], A1, b0, b1);
                }
        }
        __syncthreads();
    }

#pragma unroll
    for (int mt = 0; mt < 2; ++mt) {
        int row = g0 + mg * 32 + mt * 16 + g;
        float bs0 = bih[row] + bhh[row];
        float bs1 = bih[row + 8] + bhh[row + 8];
#pragma unroll
        for (int t2 = 0; t2 < 2; ++t2)
#pragma unroll
            for (int nt = 0; nt < 4; ++nt) {
                int col = bg * 32 + nt * 8 + 2 * tg;
                size_t base = ((size_t)(t0 + t2) * Z4z + row) * Bz + col;
                float2 v0 = make_float2(acc[t2][mt][nt][0] + bs0, acc[t2][mt][nt][1] + bs0);
                *(float2*)&g_xg[base] = v0;
                float2 v1 = make_float2(acc[t2][mt][nt][2] + bs1, acc[t2][mt][nt][3] + bs1);
                *(float2*)&g_xg[base + (size_t)8 * Bz] = v1;
            }
    }
}

// --------------------------- reset barrier + h ------------------------------
__global__ void k_reset() {
    int i = blockIdx.x * blockDim.x + threadIdx.x;
    if (i == 0) g_barrier = 0u;
    if (i < Bz * Hz / 2) {
        ((unsigned*)g_hbuf[0])[i] = 0u;
        ((unsigned*)g_hbuf[1])[i] = 0u;
    }
}

// --------------------------- persistent LSTM recurrence ---------------------
// 64 blocks x 256 threads.  Block owns 8 units (32 gate rows) x 64 batch.
// 8 warps = 4 K-slices(128) x 2 batch-halves(32).  Warp stages ONLY its own
// (ks, nh) sub-tile of h -> __syncwarp suffices before its mma.
// fp16 mma m16n8k16, fp32 accumulate.  h stored [batch][hidden] in fp16.
#define RC_SH_PITCH 520                              // halves per batch row
#define RC_SP_PITCH 72
#define RC_SH_BYTES (Bz * RC_SH_PITCH * 2)           // 66560
#define RC_SP_BYTES (4 * 32 * RC_SP_PITCH * 4)       // 36864
#define RC_ST_BYTES (Bz * 8 * 2)                     // 1024
#define SMEM_RECUR  (RC_SH_BYTES + RC_SP_BYTES + RC_ST_BYTES)

__global__ void __launch_bounds__(256, 1) k_recur(const float* __restrict__ whh,
                                                  int phase) {
    const float* xg = phase ? g_xgdec : g_xg;
    const size_t tstr = phase ? 0 : (size_t)Z4z * Bz;
    float* hs = phase ? g_hs : (float*)0;

    extern __shared__ char smc[];
    __half* s_h = (__half*)smc;                            // [64][520]
    float*  s_p = (float*)(smc + RC_SH_BYTES);             // [4 ks][32 r][72]
    __half* s_t = (__half*)(smc + RC_SH_BYTES + RC_SP_BYTES); // [64][8]

    const int tid = threadIdx.x, bid = blockIdx.x;
    const int wid = tid >> 5, lane = tid & 31;
    const int ks = wid >> 1, nh = wid & 1;
    const int g = lane >> 2, tg = lane & 3;

    // preload stationary A fragments (w_hh slice K=128, fp16 pairs along k)
    // local row r = gate*8 + ui -> global gate row = gate*512 + bid*8 + ui
    unsigned Af[2][8][4];
#pragma unroll
    for (int mt = 0; mt < 2; ++mt)
#pragma unroll
        for (int kk = 0; kk < 8; ++kk)
#pragma unroll
            for (int j = 0; j < 4; ++j) {
                int r = mt * 16 + ((j & 1) << 3) + g;
                int k0 = ks * 128 + kk * 16 + 2 * tg + ((j >> 1) << 3);
                int gate = r >> 3, ui = r & 7;
                int grow = gate * Hz + bid * 8 + ui;
                Af[mt][kk][j] = packh2(whh[(size_t)grow * Hz + k0],
                                       whh[(size_t)grow * Hz + k0 + 1]);
            }

    // cell-update mapping: warp = unit, lane = 2 consecutive batch
    const int ui = tid >> 5, b2 = (tid & 31) * 2;
    const int u_glob = bid * 8 + ui;
    float c0 = 0.f, c1 = 0.f;
    float2 xa[4];
    __syncthreads();

    for (int t = 0; t < Tz; ++t) {
        // gate preactivations (t-invariant in decoder phase: load once)
        if (t == 0 || tstr != 0) {
            const float* xp = xg + (size_t)t * tstr;
#pragma unroll
            for (int gt = 0; gt < 4; ++gt)
                xa[gt] = __ldg((const float2*)&xp[(gt * Hz + u_glob) * Bz + b2]);
        }

        // stage OWN (ks, nh) h sub-tile: 32 b-rows x 128 k halves = 8KB/warp
        {
            const uint4* src = (const uint4*)g_hbuf[t & 1];
#pragma unroll
            for (int i = 0; i < 16; ++i) {
                int flat = lane + (i << 5);        // 0..511
                int row = nh * 32 + (flat >> 4), u4 = flat & 15;
                uint4 v = __ldcg(&src[row * 64 + ks * 16 + u4]);
                *(uint4*)&s_h[row * RC_SH_PITCH + ks * 128 + u4 * 8] = v;
            }
        }
        __syncwarp();

        // mma: 2 m-tiles x 4 n-tiles (own batch half) x 8 k16 (own K-slice)
        float acc[2][4][4];
#pragma unroll
        for (int a = 0; a < 2; ++a)
#pragma unroll
            for (int b = 0; b < 4; ++b)
#pragma unroll
                for (int c = 0; c < 4; ++c) acc[a][b][c] = 0.f;

#pragma unroll
        for (int nt = 0; nt < 4; ++nt) {
            const __half* hrow = s_h + (nh * 32 + nt * 8 + g) * RC_SH_PITCH;
#pragma unroll
            for (int kk = 0; kk < 8; ++kk) {
                int k0 = ks * 128 + kk * 16 + 2 * tg;
                unsigned b0 = *(const unsigned*)&hrow[k0];
                unsigned b1 = *(const unsigned*)&hrow[k0 + 8];
                mma16(acc[0][nt], Af[0][kk], b0, b1);
                mma16(acc[1][nt], Af[1][kk], b0, b1);
            }
        }

        // store partials (float2): s_p[ks][r][nh*32 + nt*8 + 2tg]
#pragma unroll
        for (int mt = 0; mt < 2; ++mt)
#pragma unroll
            for (int nt = 0; nt < 4; ++nt) {
                int r = mt * 16 + g, b = nh * 32 + nt * 8 + 2 * tg;
                float* p = s_p + ks * (32 * RC_SP_PITCH) + r * RC_SP_PITCH + b;
                *(float2*)&p[0] = make_float2(acc[mt][nt][0], acc[mt][nt][1]);
                *(float2*)&p[8 * RC_SP_PITCH] = make_float2(acc[mt][nt][2], acc[mt][nt][3]);
            }
        __syncthreads();

        // reduce 4 K-slices + nonlinearity + cell update (2 consecutive batch)
        {
            float2 gs[4];
#pragma unroll
            for (int gt = 0; gt < 4; ++gt) {
                int r = gt * 8 + ui;
                float2 s = xa[gt];
#pragma unroll
                for (int k2 = 0; k2 < 4; ++k2) {
                    float2 v = *(const float2*)&s_p[k2 * (32 * RC_SP_PITCH) + r * RC_SP_PITCH + b2];
                    s.x += v.x; s.y += v.y;
                }
                gs[gt] = s;
            }
            float ivx = sigf(gs[0].x), fvx = sigf(gs[1].x), gvx = tanhfast(gs[2].x), ovx = sigf(gs[3].x);
            float ivy = sigf(gs[0].y), fvy = sigf(gs[1].y), gvy = tanhfast(gs[2].y), ovy = sigf(gs[3].y);
            c0 = fvx * c0 + ivx * gvx;
            c1 = fvy * c1 + ivy * gvy;
            float hx = ovx * tanhfast(c0), hy = ovy * tanhfast(c1);
            // transpose through SMEM for coalesced [b][k] half stores
            s_t[b2 * 8 + ui]       = __float2half_rn(hx);
            s_t[(b2 + 1) * 8 + ui] = __float2half_rn(hy);
            if (hs) *(float2*)&hs[((size_t)t * Hz + u_glob) * Bz + b2] = make_float2(hx, hy);
        }
        __syncthreads();

        // warp 0: store h, then lane 0 runs the grid barrier.  Other warps
        // wait at the final __syncthreads (released only after lane0's poll),
        // which orders warp0's s_t reads before any t+1 overwrite.
        if (wid == 0) {
            __half* dst = g_hbuf[(t + 1) & 1];
            uint4 v0 = *(const uint4*)&s_t[lane * 8];
            uint4 v1 = *(const uint4*)&s_t[(lane + 32) * 8];
            __stcg((uint4*)&dst[lane * Hz + bid * 8], v0);
            __stcg((uint4*)&dst[(lane + 32) * Hz + bid * 8], v1);
            __syncwarp();
            if (lane == 0) {
                asm volatile("red.release.gpu.global.add.u32 [%0], 1;"
                             :: "l"(&g_barrier) : "memory");
                unsigned tgt = (unsigned)(t + 1) * gridDim.x;
                unsigned v;
                do {
                    asm volatile("ld.acquire.gpu.global.u32 %0, [%1];"
                                 : "=r"(v) : "l"(&g_barrier) : "memory");
                } while (v < tgt);
            }
        }
        __syncthreads();
    }
}

// ------------------- mu / logvar / z (reads g_hbuf[0], [b][k] fp16) --------
__global__ void k_latent(const float* __restrict__ muw, const float* __restrict__ mub,
                         const float* __restrict__ lvw, const float* __restrict__ lvb,
                         const float* __restrict__ eps, float* __restrict__ out) {
    int b = blockIdx.x, l = threadIdx.x;        // 64 blocks x 128 threads
    __shared__ float s_h[Hz];
    for (int k = l; k < Hz; k += 128) s_h[k] = __half2float(g_hbuf[0][b * Hz + k]);
    __syncthreads();
    float m = mub[l], v = lvb[l];
    for (int k = 0; k < Hz; ++k) {
        float h = s_h[k];
        m += muw[l * Hz + k] * h;
        v += lvw[l * Hz + k] * h;
    }
    out[512000 + b * LATz + l] = m;
    out[520192 + b * LATz + l] = v;
    g_z[b * LATz + l] = m + eps[b * LATz + l] * __expf(0.5f * v);
}

// --------------------------- d = z @ dec_in_wT + b -------------------------
__global__ void k_d(const float* __restrict__ w, const float* __restrict__ bias) {
    int b = blockIdx.x, h = threadIdx.x;        // 64 x 512
    __shared__ float s_z[LATz];
    if (h < LATz) s_z[h] = g_z[b * LATz + h];
    __syncthreads();
    float a = bias[h];
#pragma unroll 4
    for (int l = 0; l < LATz; ++l) a += w[h * LATz + l] * s_z[l];
    g_d[b * Hz + h] = a;
}

// ------------------- decoder gate preacts (constant over t) ----------------
__global__ void k_xgdec(const float* __restrict__ wih, const float* __restrict__ bih,
                        const float* __restrict__ bhh) {
    int b = blockIdx.x, gc = blockIdx.y;
    int g = gc * 512 + threadIdx.x;
    __shared__ float s_d[Hz];
    s_d[threadIdx.x] = g_d[b * Hz + threadIdx.x];
    __syncthreads();
    float a = bih[g] + bhh[g];
#pragma unroll 4
    for (int k = 0; k < Hz; ++k) a += wih[(size_t)g * Hz + k] * s_d[k];
    g_xgdec[g * Bz + b] = a;
}

// --------------------------- output projection -----------------------------
__global__ void __launch_bounds__(512) k_out(const float* __restrict__ w,
                                             const float* __restrict__ bias,
                                             float* __restrict__ out) {
    int t = blockIdx.x;
    __shared__ float s_w[8 * 520];
    __shared__ float s_h[64 * 64];
    int tid = threadIdx.x;
    for (int i = tid; i < INz * Hz; i += 512) s_w[(i >> 9) * 520 + (i & 511)] = w[i];
    int b = tid >> 3, o = tid & 7;
    float acc = bias[o];
    for (int kc = 0; kc < Hz; kc += 64) {
        __syncthreads();
        for (int i = tid; i < 1024; i += 512)
            *(float4*)&s_h[i * 4] = *(const float4*)&g_hs[((size_t)t * Hz + kc) * Bz + i * 4];
        __syncthreads();
#pragma unroll
        for (int kk = 0; kk < 64; ++kk) acc += s_h[kk * 64 + b] * s_w[o * 520 + kc + kk];
    }
    out[((size_t)b * Tz + t) * INz + o] = acc;
}

// ---------------------------------------------------------------------------
extern "C" void kernel_launch(void* const* d_in, const int* in_sizes, int n_in,
                              void* d_out, int out_size) {
    const float* x        = (const float*)d_in[0];
    const float* eps      = (const float*)d_in[1];
    const float* fcin_w   = (const float*)d_in[2];
    const float* fcin_b   = (const float*)d_in[3];
    const float* enc_wih  = (const float*)d_in[4];
    const float* enc_whh  = (const float*)d_in[5];
    const float* enc_bih  = (const float*)d_in[6];
    const float* enc_bhh  = (const float*)d_in[7];
    const float* mu_w     = (const float*)d_in[8];
    const float* mu_b     = (const float*)d_in[9];
    const float* lv_w     = (const float*)d_in[10];
    const float* lv_b     = (const float*)d_in[11];
    const float* din_w    = (const float*)d_in[12];
    const float* din_b    = (const float*)d_in[13];
    const float* dec_wih  = (const float*)d_in[14];
    const float* dec_whh  = (const float*)d_in[15];
    const float* dec_bih  = (const float*)d_in[16];
    const float* dec_bhh  = (const float*)d_in[17];
    const float* out_w    = (const float*)d_in[18];
    const float* out_b    = (const float*)d_in[19];
    float* out = (float*)d_out;

    cudaFuncSetAttribute(k_recur, cudaFuncAttributeMaxDynamicSharedMemorySize, SMEM_RECUR);
    cudaFuncSetAttribute(k_xg, cudaFuncAttributeMaxDynamicSharedMemorySize, SMEM_XG);

    k_ema<<<1, 512>>>(x);                                         // #1 (also resets)
    k_hin<<<dim3(Tz, Hz / 64), 256>>>(x, fcin_w, fcin_b);         // #2
    k_xg<<<dim3(Tz / 2, Z4z / 128), 256, SMEM_XG>>>(enc_wih, enc_bih, enc_bhh); // #3
    k_recur<<<64, 256, SMEM_RECUR>>>(enc_whh, 0);                 // #4 <- ncu capture
    k_latent<<<Bz, LATz>>>(mu_w, mu_b, lv_w, lv_b, eps, out);
    k_d<<<Bz, Hz>>>(din_w, din_b);
    k_xgdec<<<dim3(Bz, 4), 512>>>(dec_wih, dec_bih, dec_bhh);
    k_reset<<<129, 256>>>();
    k_recur<<<64, 256, SMEM_RECUR>>>(dec_whh, 1);
    k_out<<<Tz, 512>>>(out_w, out_b, out);
}

// round 16
// speedup vs baseline: 1.6767x; 1.1339x over previous
#include <cuda_runtime.h>
#include <cuda_fp16.h>
#include <cuda_bf16.h>

// ---------------------------------------------------------------------------
// LSTM-VAE forward.  B=64, T=1000, IN=8, H=512, Z4=2048, LAT=128
// xg projection: tf32 mma (m16n8k8).  Recurrence: fp16 mma (m16n8k16),
// fp32 accumulate, 128 persistent blocks (4 units each), CG barrier.
// Output layout: [recon (B,T,IN) | mu (B,LAT) | logvar (B,LAT)]
// ---------------------------------------------------------------------------

#define Bz   64
#define Tz   1000
#define INz  8
#define Hz   512
#define Z4z  2048
#define LATz 128

// ------------------------- scratch (__device__ globals) --------------------
__device__ float  g_e[Bz * Tz];                      // EMA channel      (B,T)
__device__ float  g_hin[(size_t)Tz * Hz * Bz];       // enc input        (T,H,B)
__device__ float  g_xg[(size_t)Tz * Z4z * Bz];       // enc gate preacts (T,Z4,B)
__device__ float  g_xgdec[Z4z * Bz];                 // dec gate preacts (Z4,B)
__device__ __half g_hbuf[2][Bz * Hz];                // h double buffer  ([b][k], fp16)
__device__ float  g_hs[(size_t)Tz * Hz * Bz];        // dec hidden seq   (T,H,B)
__device__ float  g_z[Bz * LATz];
__device__ float  g_d[Bz * Hz];
__device__ unsigned g_barrier;

__device__ __forceinline__ float sigf(float x) { return 1.f / (1.f + __expf(-x)); }
__device__ __forceinline__ float tanhfast(float x) {
    float e = __expf(-2.f * fabsf(x));
    float r = (1.f - e) / (1.f + e);
    return copysignf(r, x);
}

// mma helpers ----------------------------------------------------------------
__device__ __forceinline__ float tf32r(float f) {
    unsigned u;
    asm("cvt.rna.tf32.f32 %0, %1;" : "=r"(u) : "f"(f));
    return __uint_as_float(u);
}
__device__ __forceinline__ void mma8(float* d, const unsigned* a, unsigned b0, unsigned b1) {
    asm volatile(
        "mma.sync.aligned.m16n8k8.row.col.f32.tf32.tf32.f32 "
        "{%0,%1,%2,%3},{%4,%5,%6,%7},{%8,%9},{%0,%1,%2,%3};"
        : "+f"(d[0]), "+f"(d[1]), "+f"(d[2]), "+f"(d[3])
        : "r"(a[0]), "r"(a[1]), "r"(a[2]), "r"(a[3]), "r"(b0), "r"(b1));
}
__device__ __forceinline__ void mma16(float* d, const unsigned* a, unsigned b0, unsigned b1) {
    asm volatile(
        "mma.sync.aligned.m16n8k16.row.col.f32.f16.f16.f32 "
        "{%0,%1,%2,%3},{%4,%5,%6,%7},{%8,%9},{%0,%1,%2,%3};"
        : "+f"(d[0]), "+f"(d[1]), "+f"(d[2]), "+f"(d[3])
        : "r"(a[0]), "r"(a[1]), "r"(a[2]), "r"(a[3]), "r"(b0), "r"(b1));
}
__device__ __forceinline__ unsigned packh2(float a, float b) {
    __half2 p = __floats2half2_rn(a, b);
    return *reinterpret_cast<unsigned*>(&p);
}

// ---------------------- EMA (parallel scan) + reset ------------------------
__global__ void k_ema(const float* __restrict__ x) {
    __shared__ float s_end[8 * 64];
    __shared__ float s_init[8 * 64];
    int tid = threadIdx.x, b = tid & 63, c = tid >> 6;

    // fused reset (h buffers are half)
    unsigned* hb0 = (unsigned*)g_hbuf[0];
    unsigned* hb1 = (unsigned*)g_hbuf[1];
    for (int i = tid; i < Bz * Hz / 2; i += 512) { hb0[i] = 0u; hb1[i] = 0u; }
    if (tid == 0) g_barrier = 0u;

    int t0 = c * 125;
    float e = 0.f;
    for (int i = 0; i < 125; ++i) {
        int t = t0 + i;
        float v = x[((size_t)b * Tz + t) * INz + 1];
        e = (c == 0 && i == 0) ? v : (0.1f * v + 0.9f * e);
        g_e[b * Tz + t] = e;
    }
    s_end[c * 64 + b] = e;
    __syncthreads();
    if (tid < 64) {
        const float P125 = 1.906849e-6f;       // 0.9^125
        float E = s_end[0 * 64 + tid];         // chunk0 is exact
        for (int cc = 1; cc < 8; ++cc) {
            s_init[cc * 64 + tid] = E;
            E = s_end[cc * 64 + tid] + E * P125;
        }
    }
    __syncthreads();
    if (c >= 1) {
        float I = s_init[c * 64 + b];
        float pw = 0.9f;
        for (int i = 0; i < 125; ++i) {
            g_e[b * Tz + t0 + i] += I * pw;
            pw *= 0.9f;
        }
    }
}

// ---------------- input FC + ReLU + positional encoding --------------------
__global__ void __launch_bounds__(256) k_hin(const float* __restrict__ x,
                                             const float* __restrict__ w,
                                             const float* __restrict__ bias) {
    int t = blockIdx.x, ht = blockIdx.y * 64;
    __shared__ float s_x[64][8];
    __shared__ float s_w[64][8];
    __shared__ float s_b[64];
    __shared__ float s_pe[64];
    int tid = threadIdx.x;

    for (int i = tid; i < 512; i += 256) {
        int bb = i >> 3, ii = i & 7;
        float v = x[((size_t)bb * Tz + t) * INz + ii];
        if (ii == 1) v = g_e[bb * Tz + t];
        s_x[bb][ii] = v;
    }
    for (int i = tid; i < 512; i += 256) {
        int hh = i >> 3, ii = i & 7;
        s_w[hh][ii] = w[(ht + hh) * INz + ii];
    }
    if (tid < 64) {
        int h = ht + tid;
        s_b[tid] = bias[h];
        int j = h >> 1;
        float div = __expf(-(float)(2 * j) * (9.2103403719761836f / 512.f));
        float ang = (float)t * div;
        s_pe[tid] = 0.1f * ((h & 1) ? cosf(ang) : sinf(ang));
    }
    __syncthreads();

    int hh = tid >> 2, bq = tid & 3;
    for (int q = 0; q < 16; ++q) {
        int bb = bq * 16 + q;
        float a = s_b[hh];
#pragma unroll
        for (int i = 0; i < 8; ++i) a += s_w[hh][i] * s_x[bb][i];
        a = fmaxf(a, 0.f) + s_pe[hh];
        g_hin[((size_t)t * Hz + ht + hh) * Bz + bb] = a;
    }
}

// ------------- encoder gate preactivations: xg = hin @ w_ihT + b -----------
#define XG_SW_PITCH 68
#define XG_SH_PITCH 72
#define SMEM_XG ((128 * XG_SW_PITCH + 2 * 64 * XG_SH_PITCH) * 4)

__global__ void __launch_bounds__(256) k_xg(const float* __restrict__ wih,
                                            const float* __restrict__ bih,
                                            const float* __restrict__ bhh) {
    extern __shared__ float sm[];
    float* s_w = sm;                               // [128][68]
    float* s_h = sm + 128 * XG_SW_PITCH;           // [2][64][72]

    const int t0 = blockIdx.x * 2, g0 = blockIdx.y * 128;
    const int tid = threadIdx.x;
    const int wid = tid >> 5, lane = tid & 31;
    const int mg = wid >> 1, bg = wid & 1;
    const int g = lane >> 2, tg = lane & 3;

    float acc[2][2][4][4];
#pragma unroll
    for (int a = 0; a < 2; ++a)
#pragma unroll
        for (int b = 0; b < 2; ++b)
#pragma unroll
            for (int c = 0; c < 4; ++c)
#pragma unroll
                for (int d = 0; d < 4; ++d) acc[a][b][c][d] = 0.f;

    for (int kc = 0; kc < Hz; kc += 64) {
#pragma unroll
        for (int i = 0; i < 8; ++i) {
            int idx = tid + i * 256;               // 0..2047
            int r = idx >> 4, k4 = idx & 15;
            float4 v = *(const float4*)&wih[(size_t)(g0 + r) * Hz + kc + k4 * 4];
            v.x = tf32r(v.x); v.y = tf32r(v.y); v.z = tf32r(v.z); v.w = tf32r(v.w);
            *(float4*)&s_w[r * XG_SW_PITCH + k4 * 4] = v;
        }
#pragma unroll
        for (int i = 0; i < 8; ++i) {
            int idx = tid + i * 256;               // 0..2047
            int t2 = idx >> 10, rem = idx & 1023;
            int kk = rem >> 4, b4 = rem & 15;
            float4 v = *(const float4*)&g_hin[((size_t)(t0 + t2) * Hz + kc + kk) * Bz + b4 * 4];
            v.x = tf32r(v.x); v.y = tf32r(v.y); v.z = tf32r(v.z); v.w = tf32r(v.w);
            *(float4*)&s_h[t2 * (64 * XG_SH_PITCH) + kk * XG_SH_PITCH + b4 * 4] = v;
        }
        __syncthreads();

#pragma unroll
        for (int kk = 0; kk < 8; ++kk) {
            unsigned A0[4], A1[4];
#pragma unroll
            for (int j = 0; j < 4; ++j) {
                int rowa = mg * 32 + ((j & 1) << 3) + g;
                int ka = kk * 8 + tg + ((j >> 1) << 2);
                A0[j] = __float_as_uint(s_w[rowa * XG_SW_PITCH + ka]);
                A1[j] = __float_as_uint(s_w[(rowa + 16) * XG_SW_PITCH + ka]);
            }
#pragma unroll
            for (int t2 = 0; t2 < 2; ++t2)
#pragma unroll
                for (int nt = 0; nt < 4; ++nt) {
                    int n = bg * 32 + nt * 8 + g;
                    const float* hb = s_h + t2 * (64 * XG_SH_PITCH);
                    unsigned b0 = __float_as_uint(hb[(kk * 8 + tg) * XG_SH_PITCH + n]);
                    unsigned b1 = __float_as_uint(hb[(kk * 8 + tg + 4) * XG_SH_PITCH + n]);
                    mma8(acc[t2][0][nt], A0, b0, b1);
                    mma8(acc[t2][1][nt], A1, b0, b1);
                }
        }
        __syncthreads();
    }

#pragma unroll
    for (int mt = 0; mt < 2; ++mt) {
        int row = g0 + mg * 32 + mt * 16 + g;
        float bs0 = bih[row] + bhh[row];
        float bs1 = bih[row + 8] + bhh[row + 8];
#pragma unroll
        for (int t2 = 0; t2 < 2; ++t2)
#pragma unroll
            for (int nt = 0; nt < 4; ++nt) {
                int col = bg * 32 + nt * 8 + 2 * tg;
                size_t base = ((size_t)(t0 + t2) * Z4z + row) * Bz + col;
                float2 v0 = make_float2(acc[t2][mt][nt][0] + bs0, acc[t2][mt][nt][1] + bs0);
                *(float2*)&g_xg[base] = v0;
                float2 v1 = make_float2(acc[t2][mt][nt][2] + bs1, acc[t2][mt][nt][3] + bs1);
                *(float2*)&g_xg[base + (size_t)8 * Bz] = v1;
            }
    }
}

// --------------------------- reset barrier + h ------------------------------
__global__ void k_reset() {
    int i = blockIdx.x * blockDim.x + threadIdx.x;
    if (i == 0) g_barrier = 0u;
    if (i < Bz * Hz / 2) {
        ((unsigned*)g_hbuf[0])[i] = 0u;
        ((unsigned*)g_hbuf[1])[i] = 0u;
    }
}

// --------------------------- persistent LSTM recurrence ---------------------
// 128 blocks x 256 threads.  Block owns 4 units (16 gate rows) x 64 batch.
// 8 warps = 4 K-slices(128) x 2 batch-halves(32).  Warp stages ONLY its own
// (ks, nh) sub-tile of h -> __syncwarp suffices before its mma.
// fp16 mma m16n8k16 (one m-tile), fp32 accumulate.  h stored [b][k] fp16.
#define RC_SH_PITCH 520                              // halves per batch row
#define RC_SP_PITCH 72
#define RC_SH_BYTES (Bz * RC_SH_PITCH * 2)           // 66560
#define RC_SP_BYTES (4 * 16 * RC_SP_PITCH * 4)       // 18432
#define RC_ST_BYTES (Bz * 4 * 2)                     // 512
#define SMEM_RECUR  (RC_SH_BYTES + RC_SP_BYTES + RC_ST_BYTES)

__global__ void __launch_bounds__(256, 1) k_recur(const float* __restrict__ whh,
                                                  int phase) {
    const float* xg = phase ? g_xgdec : g_xg;
    const size_t tstr = phase ? 0 : (size_t)Z4z * Bz;
    float* hs = phase ? g_hs : (float*)0;

    extern __shared__ char smc[];
    __half* s_h = (__half*)smc;                            // [64][520]
    float*  s_p = (float*)(smc + RC_SH_BYTES);             // [4 ks][16 r][72]
    __half* s_t = (__half*)(smc + RC_SH_BYTES + RC_SP_BYTES); // [64][4]

    const int tid = threadIdx.x, bid = blockIdx.x;
    const int wid = tid >> 5, lane = tid & 31;
    const int ks = wid >> 1, nh = wid & 1;
    const int g = lane >> 2, tg = lane & 3;

    // preload stationary A fragments (w_hh slice K=128, one m16 tile)
    // local row r = gate*4 + ui -> global gate row = gate*512 + bid*4 + ui
    unsigned Af[8][4];
#pragma unroll
    for (int kk = 0; kk < 8; ++kk)
#pragma unroll
        for (int j = 0; j < 4; ++j) {
            int r = ((j & 1) << 3) + g;            // 0..15
            int k0 = ks * 128 + kk * 16 + 2 * tg + ((j >> 1) << 3);
            int gate = r >> 2, ui4 = r & 3;
            int grow = gate * Hz + bid * 4 + ui4;
            Af[kk][j] = packh2(whh[(size_t)grow * Hz + k0],
                               whh[(size_t)grow * Hz + k0 + 1]);
        }

    // cell-update mapping: one cell per thread (4 units x 64 batch)
    const int ui = tid >> 6, bb = tid & 63;
    const int u_glob = bid * 4 + ui;
    float c0 = 0.f;
    float xa[4];
    __syncthreads();

    for (int t = 0; t < Tz; ++t) {
        // gate preactivations (t-invariant in decoder phase: load once)
        if (t == 0 || tstr != 0) {
            const float* xp = xg + (size_t)t * tstr;
#pragma unroll
            for (int gt = 0; gt < 4; ++gt)
                xa[gt] = __ldg(&xp[(gt * Hz + u_glob) * Bz + bb]);
        }

        // stage OWN (ks, nh) h sub-tile: 32 b-rows x 128 k halves = 8KB/warp
        {
            const uint4* src = (const uint4*)g_hbuf[t & 1];
#pragma unroll
            for (int i = 0; i < 16; ++i) {
                int flat = lane + (i << 5);        // 0..511
                int row = nh * 32 + (flat >> 4), u4 = flat & 15;
                uint4 v = __ldcg(&src[row * 64 + ks * 16 + u4]);
                *(uint4*)&s_h[row * RC_SH_PITCH + ks * 128 + u4 * 8] = v;
            }
        }
        __syncwarp();

        // mma: 1 m-tile x 4 n-tiles (own batch half) x 8 k16 (own K-slice)
        float acc[4][4];
#pragma unroll
        for (int b = 0; b < 4; ++b)
#pragma unroll
            for (int c = 0; c < 4; ++c) acc[b][c] = 0.f;

#pragma unroll
        for (int nt = 0; nt < 4; ++nt) {
            const __half* hrow = s_h + (nh * 32 + nt * 8 + g) * RC_SH_PITCH;
#pragma unroll
            for (int kk = 0; kk < 8; ++kk) {
                int k0 = ks * 128 + kk * 16 + 2 * tg;
                unsigned b0 = *(const unsigned*)&hrow[k0];
                unsigned b1 = *(const unsigned*)&hrow[k0 + 8];
                mma16(acc[nt], Af[kk], b0, b1);
            }
        }

        // store partials (float2): s_p[ks][r][nh*32 + nt*8 + 2tg]
#pragma unroll
        for (int nt = 0; nt < 4; ++nt) {
            int b = nh * 32 + nt * 8 + 2 * tg;
            float* p = s_p + ks * (16 * RC_SP_PITCH) + g * RC_SP_PITCH + b;
            *(float2*)&p[0] = make_float2(acc[nt][0], acc[nt][1]);
            *(float2*)&p[8 * RC_SP_PITCH] = make_float2(acc[nt][2], acc[nt][3]);
        }
        __syncthreads();

        // reduce 4 K-slices + nonlinearity + cell update (1 cell/thread)
        {
            float gs[4];
#pragma unroll
            for (int gt = 0; gt < 4; ++gt) {
                int r = gt * 4 + ui;
                float s = xa[gt];
#pragma unroll
                for (int k2 = 0; k2 < 4; ++k2)
                    s += s_p[k2 * (16 * RC_SP_PITCH) + r * RC_SP_PITCH + bb];
                gs[gt] = s;
            }
            float iv = sigf(gs[0]), fv = sigf(gs[1]), gv = tanhfast(gs[2]), ov = sigf(gs[3]);
            c0 = fv * c0 + iv * gv;
            float hx = ov * tanhfast(c0);
            // transpose through SMEM for coalesced [b][k] half stores
            s_t[bb * 4 + ui] = __float2half_rn(hx);
            if (hs) hs[((size_t)t * Hz + u_glob) * Bz + bb] = hx;
        }
        __syncthreads();

        // warp 0: store h (2 batch rows/lane, uint2 = 4 halves), then lane 0
        // runs the grid barrier.  Other warps wait at the final __syncthreads
        // (released only after lane0's poll).
        if (wid == 0) {
            __half* dst = g_hbuf[(t + 1) & 1];
            uint2 v0 = *(const uint2*)&s_t[lane * 4];
            uint2 v1 = *(const uint2*)&s_t[(lane + 32) * 4];
            __stcg((uint2*)&dst[lane * Hz + bid * 4], v0);
            __stcg((uint2*)&dst[(lane + 32) * Hz + bid * 4], v1);
            __syncwarp();
            if (lane == 0) {
                asm volatile("red.release.gpu.global.add.u32 [%0], 1;"
                             :: "l"(&g_barrier) : "memory");
                unsigned tgt = (unsigned)(t + 1) * gridDim.x;
                unsigned v;
                do {
                    asm volatile("ld.acquire.gpu.global.u32 %0, [%1];"
                                 : "=r"(v) : "l"(&g_barrier) : "memory");
                } while (v < tgt);
            }
        }
        __syncthreads();
    }
}

// ------------------- mu / logvar / z (reads g_hbuf[0], [b][k] fp16) --------
__global__ void k_latent(const float* __restrict__ muw, const float* __restrict__ mub,
                         const float* __restrict__ lvw, const float* __restrict__ lvb,
                         const float* __restrict__ eps, float* __restrict__ out) {
    int b = blockIdx.x, l = threadIdx.x;        // 64 blocks x 128 threads
    __shared__ float s_h[Hz];
    for (int k = l; k < Hz; k += 128) s_h[k] = __half2float(g_hbuf[0][b * Hz + k]);
    __syncthreads();
    float m = mub[l], v = lvb[l];
    for (int k = 0; k < Hz; ++k) {
        float h = s_h[k];
        m += muw[l * Hz + k] * h;
        v += lvw[l * Hz + k] * h;
    }
    out[512000 + b * LATz + l] = m;
    out[520192 + b * LATz + l] = v;
    g_z[b * LATz + l] = m + eps[b * LATz + l] * __expf(0.5f * v);
}

// --------------------------- d = z @ dec_in_wT + b -------------------------
__global__ void k_d(const float* __restrict__ w, const float* __restrict__ bias) {
    int b = blockIdx.x, h = threadIdx.x;        // 64 x 512
    __shared__ float s_z[LATz];
    if (h < LATz) s_z[h] = g_z[b * LATz + h];
    __syncthreads();
    float a = bias[h];
#pragma unroll 4
    for (int l = 0; l < LATz; ++l) a += w[h * LATz + l] * s_z[l];
    g_d[b * Hz + h] = a;
}

// ------------------- decoder gate preacts (constant over t) ----------------
__global__ void k_xgdec(const float* __restrict__ wih, const float* __restrict__ bih,
                        const float* __restrict__ bhh) {
    int b = blockIdx.x, gc = blockIdx.y;
    int g = gc * 512 + threadIdx.x;
    __shared__ float s_d[Hz];
    s_d[threadIdx.x] = g_d[b * Hz + threadIdx.x];
    __syncthreads();
    float a = bih[g] + bhh[g];
#pragma unroll 4
    for (int k = 0; k < Hz; ++k) a += wih[(size_t)g * Hz + k] * s_d[k];
    g_xgdec[g * Bz + b] = a;
}

// --------------------------- output projection -----------------------------
__global__ void __launch_bounds__(512) k_out(const float* __restrict__ w,
                                             const float* __restrict__ bias,
                                             float* __restrict__ out) {
    int t = blockIdx.x;
    __shared__ float s_w[8 * 520];
    __shared__ float s_h[64 * 64];
    int tid = threadIdx.x;
    for (int i = tid; i < INz * Hz; i += 512) s_w[(i >> 9) * 520 + (i & 511)] = w[i];
    int b = tid >> 3, o = tid & 7;
    float acc = bias[o];
    for (int kc = 0; kc < Hz; kc += 64) {
        __syncthreads();
        for (int i = tid; i < 1024; i += 512)
            *(float4*)&s_h[i * 4] = *(const float4*)&g_hs[((size_t)t * Hz + kc) * Bz + i * 4];
        __syncthreads();
#pragma unroll
        for (int kk = 0; kk < 64; ++kk) acc += s_h[kk * 64 + b] * s_w[o * 520 + kc + kk];
    }
    out[((size_t)b * Tz + t) * INz + o] = acc;
}

// ---------------------------------------------------------------------------
extern "C" void kernel_launch(void* const* d_in, const int* in_sizes, int n_in,
                              void* d_out, int out_size) {
    const float* x        = (const float*)d_in[0];
    const float* eps      = (const float*)d_in[1];
    const float* fcin_w   = (const float*)d_in[2];
    const float* fcin_b   = (const float*)d_in[3];
    const float* enc_wih  = (const float*)d_in[4];
    const float* enc_whh  = (const float*)d_in[5];
    const float* enc_bih  = (const float*)d_in[6];
    const float* enc_bhh  = (const float*)d_in[7];
    const float* mu_w     = (const float*)d_in[8];
    const float* mu_b     = (const float*)d_in[9];
    const float* lv_w     = (const float*)d_in[10];
    const float* lv_b     = (const float*)d_in[11];
    const float* din_w    = (const float*)d_in[12];
    const float* din_b    = (const float*)d_in[13];
    const float* dec_wih  = (const float*)d_in[14];
    const float* dec_whh  = (const float*)d_in[15];
    const float* dec_bih  = (const float*)d_in[16];
    const float* dec_bhh  = (const float*)d_in[17];
    const float* out_w    = (const float*)d_in[18];
    const float* out_b    = (const float*)d_in[19];
    float* out = (float*)d_out;

    cudaFuncSetAttribute(k_recur, cudaFuncAttributeMaxDynamicSharedMemorySize, SMEM_RECUR);
    cudaFuncSetAttribute(k_xg, cudaFuncAttributeMaxDynamicSharedMemorySize, SMEM_XG);

    k_ema<<<1, 512>>>(x);                                         // #1 (also resets)
    k_hin<<<dim3(Tz, Hz / 64), 256>>>(x, fcin_w, fcin_b);         // #2
    k_xg<<<dim3(Tz / 2, Z4z / 128), 256, SMEM_XG>>>(enc_wih, enc_bih, enc_bhh); // #3
    k_recur<<<128, 256, SMEM_RECUR>>>(enc_whh, 0);                // #4 <- ncu capture
    k_latent<<<Bz, LATz>>>(mu_w, mu_b, lv_w, lv_b, eps, out);
    k_d<<<Bz, Hz>>>(din_w, din_b);
    k_xgdec<<<dim3(Bz, 4), 512>>>(dec_wih, dec_bih, dec_bhh);
    k_reset<<<129, 256>>>();
    k_recur<<<128, 256, SMEM_RECUR>>>(dec_whh, 1);
    k_out<<<Tz, 512>>>(out_w, out_b, out);
}

// round 17
// speedup vs baseline: 2.0077x; 1.1974x over previous
#include <cuda_runtime.h>
#include <cuda_fp16.h>
#include <cuda_bf16.h>

// ---------------------------------------------------------------------------
// LSTM-VAE forward.  B=64, T=1000, IN=8, H=512, Z4=2048, LAT=128
// xg projection: tf32 mma (m16n8k8).  Recurrence: fp16 mma (m16n8k16),
// fp32 accumulate, 128 persistent blocks = 16 unit-groups x 8 batch-groups.
// Output layout: [recon (B,T,IN) | mu (B,LAT) | logvar (B,LAT)]
// ---------------------------------------------------------------------------

#define Bz   64
#define Tz   1000
#define INz  8
#define Hz   512
#define Z4z  2048
#define LATz 128

// ------------------------- scratch (__device__ globals) --------------------
__device__ float  g_e[Bz * Tz];                      // EMA channel      (B,T)
__device__ float  g_hin[(size_t)Tz * Hz * Bz];       // enc input        (T,H,B)
__device__ float  g_xg[(size_t)Tz * Z4z * Bz];       // enc gate preacts (T,Z4,B)
__device__ float  g_xgdec[Z4z * Bz];                 // dec gate preacts (Z4,B)
__device__ __half g_hbuf[2][Bz * Hz];                // h double buffer  ([b][k], fp16)
__device__ float  g_hs[(size_t)Tz * Hz * Bz];        // dec hidden seq   (T,H,B)
__device__ float  g_z[Bz * LATz];
__device__ float  g_d[Bz * Hz];
__device__ unsigned g_barrier;

__device__ __forceinline__ float sigf(float x) { return 1.f / (1.f + __expf(-x)); }
__device__ __forceinline__ float tanhfast(float x) {
    float e = __expf(-2.f * fabsf(x));
    float r = (1.f - e) / (1.f + e);
    return copysignf(r, x);
}

// mma helpers ----------------------------------------------------------------
__device__ __forceinline__ float tf32r(float f) {
    unsigned u;
    asm("cvt.rna.tf32.f32 %0, %1;" : "=r"(u) : "f"(f));
    return __uint_as_float(u);
}
__device__ __forceinline__ void mma8(float* d, const unsigned* a, unsigned b0, unsigned b1) {
    asm volatile(
        "mma.sync.aligned.m16n8k8.row.col.f32.tf32.tf32.f32 "
        "{%0,%1,%2,%3},{%4,%5,%6,%7},{%8,%9},{%0,%1,%2,%3};"
        : "+f"(d[0]), "+f"(d[1]), "+f"(d[2]), "+f"(d[3])
        : "r"(a[0]), "r"(a[1]), "r"(a[2]), "r"(a[3]), "r"(b0), "r"(b1));
}
__device__ __forceinline__ void mma16(float* d, const unsigned* a, unsigned b0, unsigned b1) {
    asm volatile(
        "mma.sync.aligned.m16n8k16.row.col.f32.f16.f16.f32 "
        "{%0,%1,%2,%3},{%4,%5,%6,%7},{%8,%9},{%0,%1,%2,%3};"
        : "+f"(d[0]), "+f"(d[1]), "+f"(d[2]), "+f"(d[3])
        : "r"(a[0]), "r"(a[1]), "r"(a[2]), "r"(a[3]), "r"(b0), "r"(b1));
}
__device__ __forceinline__ unsigned packh2(float a, float b) {
    __half2 p = __floats2half2_rn(a, b);
    return *reinterpret_cast<unsigned*>(&p);
}

// ---------------------- EMA (parallel scan) + reset ------------------------
__global__ void k_ema(const float* __restrict__ x) {
    __shared__ float s_end[8 * 64];
    __shared__ float s_init[8 * 64];
    int tid = threadIdx.x, b = tid & 63, c = tid >> 6;

    // fused reset (h buffers are half)
    unsigned* hb0 = (unsigned*)g_hbuf[0];
    unsigned* hb1 = (unsigned*)g_hbuf[1];
    for (int i = tid; i < Bz * Hz / 2; i += 512) { hb0[i] = 0u; hb1[i] = 0u; }
    if (tid == 0) g_barrier = 0u;

    int t0 = c * 125;
    float e = 0.f;
    for (int i = 0; i < 125; ++i) {
        int t = t0 + i;
        float v = x[((size_t)b * Tz + t) * INz + 1];
        e = (c == 0 && i == 0) ? v : (0.1f * v + 0.9f * e);
        g_e[b * Tz + t] = e;
    }
    s_end[c * 64 + b] = e;
    __syncthreads();
    if (tid < 64) {
        const float P125 = 1.906849e-6f;       // 0.9^125
        float E = s_end[0 * 64 + tid];         // chunk0 is exact
        for (int cc = 1; cc < 8; ++cc) {
            s_init[cc * 64 + tid] = E;
            E = s_end[cc * 64 + tid] + E * P125;
        }
    }
    __syncthreads();
    if (c >= 1) {
        float I = s_init[c * 64 + b];
        float pw = 0.9f;
        for (int i = 0; i < 125; ++i) {
            g_e[b * Tz + t0 + i] += I * pw;
            pw *= 0.9f;
        }
    }
}

// ---------------- input FC + ReLU + positional encoding --------------------
__global__ void __launch_bounds__(256) k_hin(const float* __restrict__ x,
                                             const float* __restrict__ w,
                                             const float* __restrict__ bias) {
    int t = blockIdx.x, ht = blockIdx.y * 64;
    __shared__ float s_x[64][8];
    __shared__ float s_w[64][8];
    __shared__ float s_b[64];
    __shared__ float s_pe[64];
    int tid = threadIdx.x;

    for (int i = tid; i < 512; i += 256) {
        int bb = i >> 3, ii = i & 7;
        float v = x[((size_t)bb * Tz + t) * INz + ii];
        if (ii == 1) v = g_e[bb * Tz + t];
        s_x[bb][ii] = v;
    }
    for (int i = tid; i < 512; i += 256) {
        int hh = i >> 3, ii = i & 7;
        s_w[hh][ii] = w[(ht + hh) * INz + ii];
    }
    if (tid < 64) {
        int h = ht + tid;
        s_b[tid] = bias[h];
        int j = h >> 1;
        float div = __expf(-(float)(2 * j) * (9.2103403719761836f / 512.f));
        float ang = (float)t * div;
        s_pe[tid] = 0.1f * ((h & 1) ? cosf(ang) : sinf(ang));
    }
    __syncthreads();

    int hh = tid >> 2, bq = tid & 3;
    for (int q = 0; q < 16; ++q) {
        int bb = bq * 16 + q;
        float a = s_b[hh];
#pragma unroll
        for (int i = 0; i < 8; ++i) a += s_w[hh][i] * s_x[bb][i];
        a = fmaxf(a, 0.f) + s_pe[hh];
        g_hin[((size_t)t * Hz + ht + hh) * Bz + bb] = a;
    }
}

// ------------- encoder gate preactivations: xg = hin @ w_ihT + b -----------
#define XG_SW_PITCH 68
#define XG_SH_PITCH 72
#define SMEM_XG ((128 * XG_SW_PITCH + 2 * 64 * XG_SH_PITCH) * 4)

__global__ void __launch_bounds__(256) k_xg(const float* __restrict__ wih,
                                            const float* __restrict__ bih,
                                            const float* __restrict__ bhh) {
    extern __shared__ float sm[];
    float* s_w = sm;                               // [128][68]
    float* s_h = sm + 128 * XG_SW_PITCH;           // [2][64][72]

    const int t0 = blockIdx.x * 2, g0 = blockIdx.y * 128;
    const int tid = threadIdx.x;
    const int wid = tid >> 5, lane = tid & 31;
    const int mg = wid >> 1, bg = wid & 1;
    const int g = lane >> 2, tg = lane & 3;

    float acc[2][2][4][4];
#pragma unroll
    for (int a = 0; a < 2; ++a)
#pragma unroll
        for (int b = 0; b < 2; ++b)
#pragma unroll
            for (int c = 0; c < 4; ++c)
#pragma unroll
                for (int d = 0; d < 4; ++d) acc[a][b][c][d] = 0.f;

    for (int kc = 0; kc < Hz; kc += 64) {
#pragma unroll
        for (int i = 0; i < 8; ++i) {
            int idx = tid + i * 256;               // 0..2047
            int r = idx >> 4, k4 = idx & 15;
            float4 v = *(const float4*)&wih[(size_t)(g0 + r) * Hz + kc + k4 * 4];
            v.x = tf32r(v.x); v.y = tf32r(v.y); v.z = tf32r(v.z); v.w = tf32r(v.w);
            *(float4*)&s_w[r * XG_SW_PITCH + k4 * 4] = v;
        }
#pragma unroll
        for (int i = 0; i < 8; ++i) {
            int idx = tid + i * 256;               // 0..2047
            int t2 = idx >> 10, rem = idx & 1023;
            int kk = rem >> 4, b4 = rem & 15;
            float4 v = *(const float4*)&g_hin[((size_t)(t0 + t2) * Hz + kc + kk) * Bz + b4 * 4];
            v.x = tf32r(v.x); v.y = tf32r(v.y); v.z = tf32r(v.z); v.w = tf32r(v.w);
            *(float4*)&s_h[t2 * (64 * XG_SH_PITCH) + kk * XG_SH_PITCH + b4 * 4] = v;
        }
        __syncthreads();

#pragma unroll
        for (int kk = 0; kk < 8; ++kk) {
            unsigned A0[4], A1[4];
#pragma unroll
            for (int j = 0; j < 4; ++j) {
                int rowa = mg * 32 + ((j & 1) << 3) + g;
                int ka = kk * 8 + tg + ((j >> 1) << 2);
                A0[j] = __float_as_uint(s_w[rowa * XG_SW_PITCH + ka]);
                A1[j] = __float_as_uint(s_w[(rowa + 16) * XG_SW_PITCH + ka]);
            }
#pragma unroll
            for (int t2 = 0; t2 < 2; ++t2)
#pragma unroll
                for (int nt = 0; nt < 4; ++nt) {
                    int n = bg * 32 + nt * 8 + g;
                    const float* hb = s_h + t2 * (64 * XG_SH_PITCH);
                    unsigned b0 = __float_as_uint(hb[(kk * 8 + tg) * XG_SH_PITCH + n]);
                    unsigned b1 = __float_as_uint(hb[(kk * 8 + tg + 4) * XG_SH_PITCH + n]);
                    mma8(acc[t2][0][nt], A0, b0, b1);
                    mma8(acc[t2][1][nt], A1, b0, b1);
                }
        }
        __syncthreads();
    }

#pragma unroll
    for (int mt = 0; mt < 2; ++mt) {
        int row = g0 + mg * 32 + mt * 16 + g;
        float bs0 = bih[row] + bhh[row];
        float bs1 = bih[row + 8] + bhh[row + 8];
#pragma unroll
        for (int t2 = 0; t2 < 2; ++t2)
#pragma unroll
            for (int nt = 0; nt < 4; ++nt) {
                int col = bg * 32 + nt * 8 + 2 * tg;
                size_t base = ((size_t)(t0 + t2) * Z4z + row) * Bz + col;
                float2 v0 = make_float2(acc[t2][mt][nt][0] + bs0, acc[t2][mt][nt][1] + bs0);
                *(float2*)&g_xg[base] = v0;
                float2 v1 = make_float2(acc[t2][mt][nt][2] + bs1, acc[t2][mt][nt][3] + bs1);
                *(float2*)&g_xg[base + (size_t)8 * Bz] = v1;
            }
    }
}

// --------------------------- reset barrier + h ------------------------------
__global__ void k_reset() {
    int i = blockIdx.x * blockDim.x + threadIdx.x;
    if (i == 0) g_barrier = 0u;
    if (i < Bz * Hz / 2) {
        ((unsigned*)g_hbuf[0])[i] = 0u;
        ((unsigned*)g_hbuf[1])[i] = 0u;
    }
}

// --------------------------- persistent LSTM recurrence ---------------------
// 128 blocks x 256 threads = 16 unit-groups(32) x 8 batch-groups(8).
// Each warp = one m16 gate-row tile, FULL K=512 in registers (Af[32][4]),
// N=8 batch.  No cross-warp K-reduction; 4KB gate exchange in SMEM.
// Staging: 8 batch rows x 512 k halves = 8KB/block.
#define RC_SH_PITCH 520                              // halves per batch row
#define RC_SH_BYTES (8 * RC_SH_PITCH * 2)            // 8320
#define RC_SP_BYTES (128 * 8 * 4)                    // 4096
#define RC_ST_BYTES (8 * 32 * 2)                     // 512
#define SMEM_RECUR  (RC_SH_BYTES + RC_SP_BYTES + RC_ST_BYTES)

__global__ void __launch_bounds__(256, 1) k_recur(const float* __restrict__ whh,
                                                  int phase) {
    const float* xg = phase ? g_xgdec : g_xg;
    const size_t tstr = phase ? 0 : (size_t)Z4z * Bz;
    float* hs = phase ? g_hs : (float*)0;

    extern __shared__ char smc[];
    __half* s_h = (__half*)smc;                            // [8 b][520]
    float*  s_p = (float*)(smc + RC_SH_BYTES);             // [128 r][8]
    __half* s_t = (__half*)(smc + RC_SH_BYTES + RC_SP_BYTES); // [8 b][32 u]

    const int tid = threadIdx.x, bid = blockIdx.x;
    const int wid = tid >> 5, lane = tid & 31;
    const int mg = bid >> 3, ng = bid & 7;
    const int g = lane >> 2, tg = lane & 3;

    // stationary A fragments: warp wid = m-tile (local gate rows wid*16..+15)
    // local row r = wid*16 + rt -> gate = r>>5, u_local = r&31
    // global w_hh row = gate*512 + mg*32 + u_local
    unsigned Af[32][4];
#pragma unroll
    for (int kk = 0; kk < 32; ++kk)
#pragma unroll
        for (int j = 0; j < 4; ++j) {
            int rt = ((j & 1) << 3) + g;
            int gate = wid >> 1;
            int u_local = (wid & 1) * 16 + rt;
            int grow = gate * Hz + mg * 32 + u_local;
            int k0 = kk * 16 + 2 * tg + ((j >> 1) << 3);
            Af[kk][j] = packh2(whh[(size_t)grow * Hz + k0],
                               whh[(size_t)grow * Hz + k0 + 1]);
        }

    // cell-update mapping: thread = (unit uu 0..31, batch bb 0..7)
    const int uu = tid >> 3, bb = tid & 7;
    const int u_glob = mg * 32 + uu, b_glob = ng * 8 + bb;
    float c0 = 0.f;
    float xa[4];
    __syncthreads();

    for (int t = 0; t < Tz; ++t) {
        // gate preactivations (t-invariant in decoder phase: load once)
        if (t == 0 || tstr != 0) {
            const float* xp = xg + (size_t)t * tstr;
#pragma unroll
            for (int gt = 0; gt < 4; ++gt)
                xa[gt] = __ldg(&xp[(gt * Hz + u_glob) * Bz + b_glob]);
        }

        // stage own 8 batch rows of h: 512 uint4, 2 per thread
        {
            const uint4* src = (const uint4*)g_hbuf[t & 1];
#pragma unroll
            for (int i = 0; i < 2; ++i) {
                int idx = tid + (i << 8);          // 0..511
                int row = idx >> 6, kq = idx & 63;
                uint4 v = __ldcg(&src[(ng * 8 + row) * 64 + kq]);
                *(uint4*)&s_h[row * RC_SH_PITCH + kq * 8] = v;
            }
        }
        __syncthreads();

        // mma: own m16 tile, n=8, K=512 (32 k16 steps, 4 independent chains)
        float acc[4][4];
#pragma unroll
        for (int ch = 0; ch < 4; ++ch)
#pragma unroll
            for (int c = 0; c < 4; ++c) acc[ch][c] = 0.f;

#pragma unroll
        for (int kk = 0; kk < 32; ++kk) {
            int k0 = kk * 16 + 2 * tg;
            unsigned b0 = *(const unsigned*)&s_h[g * RC_SH_PITCH + k0];
            unsigned b1 = *(const unsigned*)&s_h[g * RC_SH_PITCH + k0 + 8];
            mma16(acc[kk & 3], Af[kk], b0, b1);
        }
#pragma unroll
        for (int c = 0; c < 4; ++c)
            acc[0][c] = (acc[0][c] + acc[1][c]) + (acc[2][c] + acc[3][c]);

        // gate exchange: s_p[local row][batch]
        {
            int r0 = wid * 16 + g;
            *(float2*)&s_p[r0 * 8 + 2 * tg] = make_float2(acc[0][0], acc[0][1]);
            *(float2*)&s_p[(r0 + 8) * 8 + 2 * tg] = make_float2(acc[0][2], acc[0][3]);
        }
        __syncthreads();

        // cell update (1 cell/thread)
        {
            float gs[4];
#pragma unroll
            for (int gt = 0; gt < 4; ++gt)
                gs[gt] = xa[gt] + s_p[(gt * 32 + uu) * 8 + bb];
            float iv = sigf(gs[0]), fv = sigf(gs[1]), gv = tanhfast(gs[2]), ov = sigf(gs[3]);
            c0 = fv * c0 + iv * gv;
            float hx = ov * tanhfast(c0);
            s_t[bb * 32 + uu] = __float2half_rn(hx);
            if (hs) hs[((size_t)t * Hz + u_glob) * Bz + b_glob] = hx;
        }
        __syncthreads();

        // warp 0: store h block (8 batch rows x 32 units), then grid barrier
        if (wid == 0) {
            int row = lane >> 2, q = lane & 3;
            uint4 v = *(const uint4*)&s_t[row * 32 + q * 8];
            __stcg((uint4*)&g_hbuf[(t + 1) & 1][(ng * 8 + row) * Hz + mg * 32 + q * 8], v);
            __syncwarp();
            if (lane == 0) {
                asm volatile("red.release.gpu.global.add.u32 [%0], 1;"
                             :: "l"(&g_barrier) : "memory");
                unsigned tgt = (unsigned)(t + 1) * gridDim.x;
                unsigned v2;
                do {
                    asm volatile("ld.acquire.gpu.global.u32 %0, [%1];"
                                 : "=r"(v2) : "l"(&g_barrier) : "memory");
                } while (v2 < tgt);
            }
        }
        __syncthreads();
    }
}

// ------------------- mu / logvar / z (reads g_hbuf[0], [b][k] fp16) --------
__global__ void k_latent(const float* __restrict__ muw, const float* __restrict__ mub,
                         const float* __restrict__ lvw, const float* __restrict__ lvb,
                         const float* __restrict__ eps, float* __restrict__ out) {
    int b = blockIdx.x, l = threadIdx.x;        // 64 blocks x 128 threads
    __shared__ float s_h[Hz];
    for (int k = l; k < Hz; k += 128) s_h[k] = __half2float(g_hbuf[0][b * Hz + k]);
    __syncthreads();
    float m = mub[l], v = lvb[l];
    for (int k = 0; k < Hz; ++k) {
        float h = s_h[k];
        m += muw[l * Hz + k] * h;
        v += lvw[l * Hz + k] * h;
    }
    out[512000 + b * LATz + l] = m;
    out[520192 + b * LATz + l] = v;
    g_z[b * LATz + l] = m + eps[b * LATz + l] * __expf(0.5f * v);
}

// --------------------------- d = z @ dec_in_wT + b -------------------------
__global__ void k_d(const float* __restrict__ w, const float* __restrict__ bias) {
    int b = blockIdx.x, h = threadIdx.x;        // 64 x 512
    __shared__ float s_z[LATz];
    if (h < LATz) s_z[h] = g_z[b * LATz + h];
    __syncthreads();
    float a = bias[h];
#pragma unroll 4
    for (int l = 0; l < LATz; ++l) a += w[h * LATz + l] * s_z[l];
    g_d[b * Hz + h] = a;
}

// ------------------- decoder gate preacts (constant over t) ----------------
__global__ void k_xgdec(const float* __restrict__ wih, const float* __restrict__ bih,
                        const float* __restrict__ bhh) {
    int b = blockIdx.x, gc = blockIdx.y;
    int g = gc * 512 + threadIdx.x;
    __shared__ float s_d[Hz];
    s_d[threadIdx.x] = g_d[b * Hz + threadIdx.x];
    __syncthreads();
    float a = bih[g] + bhh[g];
#pragma unroll 4
    for (int k = 0; k < Hz; ++k) a += wih[(size_t)g * Hz + k] * s_d[k];
    g_xgdec[g * Bz + b] = a;
}

// --------------------------- output projection -----------------------------
__global__ void __launch_bounds__(512) k_out(const float* __restrict__ w,
                                             const float* __restrict__ bias,
                                             float* __restrict__ out) {
    int t = blockIdx.x;
    __shared__ float s_w[8 * 520];
    __shared__ float s_h[64 * 64];
    int tid = threadIdx.x;
    for (int i = tid; i < INz * Hz; i += 512) s_w[(i >> 9) * 520 + (i & 511)] = w[i];
    int b = tid >> 3, o = tid & 7;
    float acc = bias[o];
    for (int kc = 0; kc < Hz; kc += 64) {
        __syncthreads();
        for (int i = tid; i < 1024; i += 512)
            *(float4*)&s_h[i * 4] = *(const float4*)&g_hs[((size_t)t * Hz + kc) * Bz + i * 4];
        __syncthreads();
#pragma unroll
        for (int kk = 0; kk < 64; ++kk) acc += s_h[kk * 64 + b] * s_w[o * 520 + kc + kk];
    }
    out[((size_t)b * Tz + t) * INz + o] = acc;
}

// ---------------------------------------------------------------------------
extern "C" void kernel_launch(void* const* d_in, const int* in_sizes, int n_in,
                              void* d_out, int out_size) {
    const float* x        = (const float*)d_in[0];
    const float* eps      = (const float*)d_in[1];
    const float* fcin_w   = (const float*)d_in[2];
    const float* fcin_b   = (const float*)d_in[3];
    const float* enc_wih  = (const float*)d_in[4];
    const float* enc_whh  = (const float*)d_in[5];
    const float* enc_bih  = (const float*)d_in[6];
    const float* enc_bhh  = (const float*)d_in[7];
    const float* mu_w     = (const float*)d_in[8];
    const float* mu_b     = (const float*)d_in[9];
    const float* lv_w     = (const float*)d_in[10];
    const float* lv_b     = (const float*)d_in[11];
    const float* din_w    = (const float*)d_in[12];
    const float* din_b    = (const float*)d_in[13];
    const float* dec_wih  = (const float*)d_in[14];
    const float* dec_whh  = (const float*)d_in[15];
    const float* dec_bih  = (const float*)d_in[16];
    const float* dec_bhh  = (const float*)d_in[17];
    const float* out_w    = (const float*)d_in[18];
    const float* out_b    = (const float*)d_in[19];
    float* out = (float*)d_out;

    cudaFuncSetAttribute(k_recur, cudaFuncAttributeMaxDynamicSharedMemorySize, SMEM_RECUR);
    cudaFuncSetAttribute(k_xg, cudaFuncAttributeMaxDynamicSharedMemorySize, SMEM_XG);

    k_ema<<<1, 512>>>(x);                                         // #1 (also resets)
    k_hin<<<dim3(Tz, Hz / 64), 256>>>(x, fcin_w, fcin_b);         // #2
    k_xg<<<dim3(Tz / 2, Z4z / 128), 256, SMEM_XG>>>(enc_wih, enc_bih, enc_bhh); // #3
    k_recur<<<128, 256, SMEM_RECUR>>>(enc_whh, 0);                // #4 <- ncu capture
    k_latent<<<Bz, LATz>>>(mu_w, mu_b, lv_w, lv_b, eps, out);
    k_d<<<Bz, Hz>>>(din_w, din_b);
    k_xgdec<<<dim3(Bz, 4), 512>>>(dec_wih, dec_bih, dec_bhh);
    k_reset<<<129, 256>>>();
    k_recur<<<128, 256, SMEM_RECUR>>>(dec_whh, 1);
    k_out<<<Tz, 512>>>(out_w, out_b, out);
}